// round 11
// baseline (speedup 1.0000x reference)
#include <cuda_runtime.h>
#include <cuda_fp16.h>

#define NV     101          // tokens incl. start symbol (start = 100)
#define UMX    256
#define NSTEPS 257
#define G3     3072
#define NCTA   128
#define NTHR   512

typedef unsigned u32;

// ---------------- static device scratch (no runtime allocation) ----------------
// Fragment-packed fp16 hi/lo weights.
// g_W0p: phase A (K=1024): n-rows 0..3071 = W_hh layer0 (r,z,n), 3072..4095 = lin_W.
//   [ntile(512)][ktile(64)][lane(32)] : uint4 = {Whi.b0, Whi.b1, Wlo.b0, Wlo.b1}
__device__ __align__(16) uint4 g_W0p[512 * 64 * 32];            // 16 MB
// g_W12p: layers 1,2 (K=2048): per layer n-row q*1024+j:
//   q=0:[Wih_r|Whh_r] q=1:[Wih_z|Whh_z] q=2:[Wih_n|0] q=3:[0|Whh_n]
//   [layer(2)][ntile(512)][ktile(128)][lane(32)]
__device__ __align__(16) uint4 g_W12p[2 * 512 * 128 * 32];      // 64 MB
// Fragment-packed fp16 activations (single plane): [l(3)][par(2)][mtile(4)][ktile(128)][lane(32)]
__device__ __align__(16) uint4 g_A[3 * 2 * 4 * 128 * 32];       // 1.5 MB
__device__ float g_T[NV * G3];          // layer0 gi table (incl b_ih0), fp32
__device__ float g_stf[3 * 64 * 1024];  // fp32 states [l][b][j]
__device__ unsigned g_bar;

// ---------------- grid barrier: release-arrive + acquire-poll ----------------
__device__ __forceinline__ void gridbar() {
    __syncthreads();
    if (threadIdx.x == 0) {
        u32 ticket;
        asm volatile("atom.add.release.gpu.global.u32 %0, [%1], 1;"
                     : "=r"(ticket) : "l"(&g_bar) : "memory");
        u32 target = ((ticket + NCTA) / NCTA) * NCTA;
        u32 cur;
        do {
            asm volatile("ld.acquire.gpu.global.u32 %0, [%1];"
                         : "=r"(cur) : "l"(&g_bar) : "memory");
        } while (cur < target);
    }
    __syncthreads();
}

__device__ __forceinline__ float sigm(float t) { return 1.0f / (1.0f + expf(-t)); }

// split fp32 -> (hi, lo) fp16 bit patterns
__device__ __forceinline__ void sph(float w, u32& hb, u32& lb) {
    __half h = __float2half_rn(w);
    hb = (u32)__half_as_ushort(h);
    lb = (u32)__half_as_ushort(__float2half_rn(w - __half2float(h)));
}
__device__ __forceinline__ uint4 pack4h(float a, float b, float c, float d) {
    u32 ah, al, bh, bl, ch, cl, dh, dl;
    sph(a, ah, al); sph(b, bh, bl); sph(c, ch, cl); sph(d, dh, dl);
    uint4 v;
    v.x = ah | (bh << 16);   // hi b0 (k0, k0+1)
    v.y = ch | (dh << 16);   // hi b1 (k0+8, k0+9)
    v.z = al | (bl << 16);   // lo b0
    v.w = cl | (dl << 16);   // lo b1
    return v;
}

// A-buffer offset (uint4 units, excluding lane)
__device__ __forceinline__ size_t aoff(int l, int par, int mt, int kt) {
    return (size_t)((((l * 2 + par) * 4 + mt) * 128 + kt)) * 32;
}
// Write activation element (b, c) as fp16 into fragment layout
__device__ __forceinline__ void storeA(int l, int par, int b, int c, float v) {
    int mt = b >> 4, mr = b & 15, kt = c >> 4, kk = c & 15;
    int lane = (mr & 7) * 4 + ((kk & 7) >> 1);
    int slot = (mr >> 3) + ((kk >> 3) << 1);
    __half* p = (__half*)(g_A + aoff(l, par, mt, kt) + lane);
    p[slot * 2 + (kk & 1)] = __float2half_rn(v);
}

// ---------------- cp.async helpers (per-lane 16B, zero registers in flight) ----------------
__device__ __forceinline__ void cpa16(u32 dst_s, const void* src) {
    asm volatile("cp.async.cg.shared.global [%0], [%1], 16;"
                 :: "r"(dst_s), "l"(src) : "memory");
}
#define CP_COMMIT() asm volatile("cp.async.commit_group;" ::: "memory")
#define CP_WAIT2()  asm volatile("cp.async.wait_group 2;"  ::: "memory")

// ---------------- mma.m16n8k16 fp16 ----------------
__device__ __forceinline__ void mma_f16(float* d, const uint4& a, u32 b0, u32 b1) {
    asm volatile(
        "mma.sync.aligned.m16n8k16.row.col.f32.f16.f16.f32 "
        "{%0,%1,%2,%3}, {%4,%5,%6,%7}, {%8,%9}, {%0,%1,%2,%3};"
        : "+f"(d[0]), "+f"(d[1]), "+f"(d[2]), "+f"(d[3])
        : "r"(a.x), "r"(a.y), "r"(a.z), "r"(a.w), "r"(b0), "r"(b1));
}
// 2-chain combine + store 16x8 tile into smem slab (float[128])
__device__ __forceinline__ void stD2(float* base, int rr, int cc,
                                     const float* d0, const float* d1) {
    base[rr * 8 + cc]           = d0[0] + d1[0];
    base[rr * 8 + cc + 1]       = d0[1] + d1[1];
    base[(rr + 8) * 8 + cc]     = d0[2] + d1[2];
    base[(rr + 8) * 8 + cc + 1] = d0[3] + d1[3];
}

#define SMEM_SD_FLOATS 12288
#define SMEM_TOTAL     (49152 + 131072)   // 48 KB sD + 128 KB B-rings

// ================================================================================
__global__ void __launch_bounds__(NTHR, 1)
decoder_kernel(const int*   __restrict__ y,
               const float* __restrict__ embed,
               const float* __restrict__ W_ih,
               const float* __restrict__ W_hh,
               const float* __restrict__ b_ih,
               const float* __restrict__ b_hh,
               const float* __restrict__ init_state,
               const float* __restrict__ lin_W,
               const float* __restrict__ lin_b,
               float*       __restrict__ out)
{
    extern __shared__ float sbuf[];     // [0,48K): sD ; [48K,176K): per-warp B rings
    const int tid  = threadIdx.x;
    const int lane = tid & 31;
    const int wid  = tid >> 5;          // 0..15
    const int mwA  = wid & 3;           // phase A: m-tile
    const int ksA  = wid >> 2;          // phase A: k-slice 0..3 (16 ktiles each)
    const int mpB  = wid & 1;           // B/C: m-half
    const int ksB  = wid >> 1;          // B/C: k-slice 0..7 (16 ktiles each)
    const int cta  = blockIdx.x;
    const int gt   = cta * NTHR + tid;
    const int GS   = NCTA * NTHR;
    const int rr   = lane >> 2, cc = (lane & 3) << 1;

    // per-warp ring: 16 slots (stream*4+stage) x 32 uint4 = 8 KB
    uint4* wring = (uint4*)((char*)sbuf + 49152) + (size_t)wid * 16 * 32;
    const u32 rbase = (u32)__cvta_generic_to_shared(wring + lane);

    // phase A view: [s(4)][mt(4)][q(4)][128]
    #define SA(s, mt, q) (sbuf + (((s) * 4 + (mt)) * 4 + (q)) * 128)
    // B/C view: [s(8)][mt(4)][g(3)][128]; g=2 holds i_n for s<4, h_n for s>=4
    #define SB(s, mt, g) (sbuf + (((s) * 4 + (mt)) * 3 + (g)) * 128)

    // ================= PROLOGUE =================
    for (int idx = gt; idx < 512 * 64 * 32; idx += GS) {
        int ln = idx & 31, t = (idx >> 5) & 63, NT = idx >> 11;
        int n  = NT * 8 + (ln >> 2);
        int k0 = t * 16 + ((ln & 3) << 1);
        const float* src = (n < 3072) ? (W_hh + (size_t)n * 1024)
                                      : (lin_W + (size_t)(n - 3072) * 1024);
        g_W0p[idx] = pack4h(src[k0], src[k0 + 1], src[k0 + 8], src[k0 + 9]);
    }
    for (int idx = gt; idx < 2 * 512 * 128 * 32; idx += GS) {
        int ln = idx & 31, t = (idx >> 5) & 127, NT = (idx >> 12) & 511, ll = idx >> 21;
        int n  = NT * 8 + (ln >> 2);
        int qq = n >> 10, jj = n & 1023;
        int k0 = t * 16 + ((ln & 3) << 1);
        int lay = ll + 1;
        float w[4];
#pragma unroll
        for (int i = 0; i < 4; ++i) {
            int k = k0 + ((i >> 1) << 3) + (i & 1);   // k0, k0+1, k0+8, k0+9
            float v = 0.0f;
            if (qq < 2) {
                v = (k < 1024) ? W_ih[((size_t)lay * 3072 + qq * 1024 + jj) * 1024 + k]
                               : W_hh[((size_t)lay * 3072 + qq * 1024 + jj) * 1024 + k - 1024];
            } else if (qq == 2) {
                if (k < 1024) v = W_ih[((size_t)lay * 3072 + 2048 + jj) * 1024 + k];
            } else {
                if (k >= 1024) v = W_hh[((size_t)lay * 3072 + 2048 + jj) * 1024 + k - 1024];
            }
            w[i] = v;
        }
        g_W12p[idx] = pack4h(w[0], w[1], w[2], w[3]);
    }
    // fp32 token table: T[v][row] = embed[v] . W_ih0[row] + b_ih0[row]
    for (int idx = gt; idx < 3072 * 128; idx += GS) {
        int row = idx >> 7, v = idx & 127;
        if (v < NV) {
            const float* e = embed + (size_t)v * 1024;
            const float* w = W_ih + (size_t)row * 1024;
            float a0 = 0, a1 = 0, a2 = 0, a3 = 0;
            for (int k = 0; k < 1024; k += 4) {
                a0 += e[k] * w[k];         a1 += e[k + 1] * w[k + 1];
                a2 += e[k + 2] * w[k + 2]; a3 += e[k + 3] * w[k + 3];
            }
            g_T[v * G3 + row] = (a0 + a1) + (a2 + a3) + b_ih[row];
        }
    }
    for (int idx = gt; idx < 3 * 64 * 1024; idx += GS) {
        int l = idx >> 16, r = idx & 65535, b = r >> 10, j = r & 1023;
        float v = init_state[l * 1024 + j];
        g_stf[idx] = v;
        storeA(l, 0, b, (l == 0) ? j : (1024 + j), v);
    }
    gridbar();

    // ================= STEP LOOP =================
    for (int u = 0; u < NSTEPS; ++u) {
        const int par = u & 1;

        // ----- phase A: layer0 h-GEMM (r,z,n on h0) + lin of u-1 (on h2), K=1024 -----
        {
            const int t0 = ksA * 16;
            const uint4* A0 = g_A + aoff(0, par, mwA, t0) + lane;
            const uint4* A2 = g_A + aoff(2, par, mwA, 64 + t0) + lane;
            const uint4* B0g = g_W0p + ((size_t)(0 * 128 + cta) * 64 + t0) * 32 + lane;
            const uint4* B1g = g_W0p + ((size_t)(1 * 128 + cta) * 64 + t0) * 32 + lane;
            const uint4* B2g = g_W0p + ((size_t)(2 * 128 + cta) * 64 + t0) * 32 + lane;
            const uint4* B3g = g_W0p + ((size_t)(3 * 128 + cta) * 64 + t0) * 32 + lane;
            float d0a[4] = {}, d0b[4] = {}, d1a[4] = {}, d1b[4] = {};
            float d2a[4] = {}, d2b[4] = {}, d3a[4] = {}, d3b[4] = {};
#pragma unroll
            for (int t = 0; t < 3; ++t) {
                cpa16(rbase + (u32)((0 * 4 + t) * 512), B0g + t * 32);
                cpa16(rbase + (u32)((1 * 4 + t) * 512), B1g + t * 32);
                cpa16(rbase + (u32)((2 * 4 + t) * 512), B2g + t * 32);
                cpa16(rbase + (u32)((3 * 4 + t) * 512), B3g + t * 32);
                CP_COMMIT();
            }
#pragma unroll 1
            for (int i = 0; i < 16; ++i) {
                CP_WAIT2();
                const int st = i & 3;
                uint4 b0 = wring[(0 * 4 + st) * 32 + lane];
                uint4 b1 = wring[(1 * 4 + st) * 32 + lane];
                uint4 b2 = wring[(2 * 4 + st) * 32 + lane];
                uint4 b3 = wring[(3 * 4 + st) * 32 + lane];
                const int tn = i + 3;
                if (tn < 16) {
                    const u32 sn = (u32)(tn & 3) * 512;
                    cpa16(rbase + 0 * 2048 + sn, B0g + tn * 32);
                    cpa16(rbase + 1 * 2048 + sn, B1g + tn * 32);
                    cpa16(rbase + 2 * 2048 + sn, B2g + tn * 32);
                    cpa16(rbase + 3 * 2048 + sn, B3g + tn * 32);
                }
                CP_COMMIT();
                uint4 a = A0[i * 32], c = A2[i * 32];
                mma_f16(d0a, a, b0.x, b0.y); mma_f16(d0b, a, b0.z, b0.w);
                mma_f16(d1a, a, b1.x, b1.y); mma_f16(d1b, a, b1.z, b1.w);
                mma_f16(d2a, a, b2.x, b2.y); mma_f16(d2b, a, b2.z, b2.w);
                mma_f16(d3a, c, b3.x, b3.y); mma_f16(d3b, c, b3.z, b3.w);
            }
            stD2(SA(ksA, mwA, 0), rr, cc, d0a, d0b);
            stD2(SA(ksA, mwA, 1), rr, cc, d1a, d1b);
            stD2(SA(ksA, mwA, 2), rr, cc, d2a, d2b);
            stD2(SA(ksA, mwA, 3), rr, cc, d3a, d3b);
        }
        __syncthreads();
        {   // epilogue A: GRU layer0 + out[u-1]
            int b = tid >> 3, jj = tid & 7, mm = b >> 4, r2 = b & 15;
            float Dr = 0, Dz = 0, Dn = 0, Do = 0;
#pragma unroll
            for (int s = 0; s < 4; ++s) {
                Dr += SA(s, mm, 0)[r2 * 8 + jj];
                Dz += SA(s, mm, 1)[r2 * 8 + jj];
                Dn += SA(s, mm, 2)[r2 * 8 + jj];
                Do += SA(s, mm, 3)[r2 * 8 + jj];
            }
            int jcol = cta * 8 + jj;
            int tok = (u == 0) ? (NV - 1) : y[b * UMX + (u - 1)];
            const float* Tv = g_T + (size_t)tok * G3;
            float r = sigm(Tv[jcol] + Dr + b_hh[jcol]);
            float z = sigm(Tv[1024 + jcol] + Dz + b_hh[1024 + jcol]);
            float n = tanhf(Tv[2048 + jcol] + r * (Dn + b_hh[2048 + jcol]));
            float hp = g_stf[b * 1024 + jcol];
            float h = (1.0f - z) * n + z * hp;
            g_stf[b * 1024 + jcol] = h;
            storeA(1, par, b, jcol, h);          // x for layer1 this step
            storeA(0, par ^ 1, b, jcol, h);      // h0 for next step
            if (u > 0)
                out[(size_t)b * NSTEPS * 1024 + (size_t)(u - 1) * 1024 + jcol] = Do + lin_b[jcol];
        }
        gridbar();

        // ----- phases B, C: layers 1, 2 (K=2048; warp = (m-half, k-slice of 8)) -----
#pragma unroll 1
        for (int l = 1; l <= 2; ++l) {
            {
                const int t0  = ksB * 16;
                const int g2q = 2 + (ksB >> 2);        // i_n for ks<4, h_n for ks>=4
                const int mt0 = mpB * 2;
                const uint4* A   = g_A + aoff(l, par, mt0, t0) + lane;
                const uint4* B0g = g_W12p + ((size_t)((l - 1) * 512 + 0 * 128 + cta) * 128 + t0) * 32 + lane;
                const uint4* B1g = g_W12p + ((size_t)((l - 1) * 512 + 1 * 128 + cta) * 128 + t0) * 32 + lane;
                const uint4* B2g = g_W12p + ((size_t)((l - 1) * 512 + g2q * 128 + cta) * 128 + t0) * 32 + lane;
                float m0g0a[4] = {}, m0g0b[4] = {}, m0g1a[4] = {}, m0g1b[4] = {};
                float m0g2a[4] = {}, m0g2b[4] = {};
                float m1g0a[4] = {}, m1g0b[4] = {}, m1g1a[4] = {}, m1g1b[4] = {};
                float m1g2a[4] = {}, m1g2b[4] = {};
#pragma unroll
                for (int t = 0; t < 3; ++t) {
                    cpa16(rbase + (u32)((0 * 4 + t) * 512), B0g + t * 32);
                    cpa16(rbase + (u32)((1 * 4 + t) * 512), B1g + t * 32);
                    cpa16(rbase + (u32)((2 * 4 + t) * 512), B2g + t * 32);
                    CP_COMMIT();
                }
#pragma unroll 1
                for (int i = 0; i < 16; ++i) {
                    CP_WAIT2();
                    const int st = i & 3;
                    uint4 b0 = wring[(0 * 4 + st) * 32 + lane];
                    uint4 b1 = wring[(1 * 4 + st) * 32 + lane];
                    uint4 b2 = wring[(2 * 4 + st) * 32 + lane];
                    const int tn = i + 3;
                    if (tn < 16) {
                        const u32 sn = (u32)(tn & 3) * 512;
                        cpa16(rbase + 0 * 2048 + sn, B0g + tn * 32);
                        cpa16(rbase + 1 * 2048 + sn, B1g + tn * 32);
                        cpa16(rbase + 2 * 2048 + sn, B2g + tn * 32);
                    }
                    CP_COMMIT();
                    uint4 a0 = A[i * 32], a1 = A[i * 32 + 128 * 32];
                    mma_f16(m0g0a, a0, b0.x, b0.y); mma_f16(m0g0b, a0, b0.z, b0.w);
                    mma_f16(m0g1a, a0, b1.x, b1.y); mma_f16(m0g1b, a0, b1.z, b1.w);
                    mma_f16(m0g2a, a0, b2.x, b2.y); mma_f16(m0g2b, a0, b2.z, b2.w);
                    mma_f16(m1g0a, a1, b0.x, b0.y); mma_f16(m1g0b, a1, b0.z, b0.w);
                    mma_f16(m1g1a, a1, b1.x, b1.y); mma_f16(m1g1b, a1, b1.z, b1.w);
                    mma_f16(m1g2a, a1, b2.x, b2.y); mma_f16(m1g2b, a1, b2.z, b2.w);
                }
                stD2(SB(ksB, mt0, 0), rr, cc, m0g0a, m0g0b);
                stD2(SB(ksB, mt0, 1), rr, cc, m0g1a, m0g1b);
                stD2(SB(ksB, mt0, 2), rr, cc, m0g2a, m0g2b);
                stD2(SB(ksB, mt0 + 1, 0), rr, cc, m1g0a, m1g0b);
                stD2(SB(ksB, mt0 + 1, 1), rr, cc, m1g1a, m1g1b);
                stD2(SB(ksB, mt0 + 1, 2), rr, cc, m1g2a, m1g2b);
            }
            __syncthreads();
            {   // epilogue: GRU layer l
                int b = tid >> 3, jj = tid & 7, mm = b >> 4, r2 = b & 15;
                float Gr = 0, Gz = 0, Gi = 0, Gh = 0;
#pragma unroll
                for (int s = 0; s < 8; ++s) {
                    Gr += SB(s, mm, 0)[r2 * 8 + jj];
                    Gz += SB(s, mm, 1)[r2 * 8 + jj];
                }
#pragma unroll
                for (int s = 0; s < 4; ++s) Gi += SB(s, mm, 2)[r2 * 8 + jj];
#pragma unroll
                for (int s = 4; s < 8; ++s) Gh += SB(s, mm, 2)[r2 * 8 + jj];
                int jcol = cta * 8 + jj;
                const float* bi  = b_ih + l * G3;
                const float* bhv = b_hh + l * G3;
                float r = sigm(Gr + bi[jcol] + bhv[jcol]);
                float z = sigm(Gz + bi[1024 + jcol] + bhv[1024 + jcol]);
                float n = tanhf(Gi + bi[2048 + jcol] + r * (Gh + bhv[2048 + jcol]));
                float hp = g_stf[(l * 64 + b) * 1024 + jcol];
                float h = (1.0f - z) * n + z * hp;
                g_stf[(l * 64 + b) * 1024 + jcol] = h;
                if (l == 1) {
                    storeA(2, par, b, jcol, h);              // x for layer2 this step
                    storeA(1, par ^ 1, b, 1024 + jcol, h);   // h1 next step
                } else {
                    storeA(2, par ^ 1, b, 1024 + jcol, h);   // h2: lin + layer2 next step
                }
            }
            gridbar();
        }
    }

    // ================= FINAL OUTPUT (u = NSTEPS-1) =================
    {
        const int t0 = ksA * 16;
        const uint4* A2 = g_A + aoff(2, NSTEPS & 1, mwA, 64 + t0) + lane;
        const uint4* B3 = g_W0p + ((size_t)(384 + cta) * 64 + t0) * 32 + lane;
        float da[4] = {}, db[4] = {};
#pragma unroll 2
        for (int i = 0; i < 16; ++i) {
            uint4 c = A2[i * 32], b3 = B3[i * 32];
            mma_f16(da, c, b3.x, b3.y);
            mma_f16(db, c, b3.z, b3.w);
        }
        stD2(SA(ksA, mwA, 0), rr, cc, da, db);
    }
    __syncthreads();
    {
        int b = tid >> 3, jj = tid & 7, mm = b >> 4, r2 = b & 15;
        float Do = 0;
#pragma unroll
        for (int s = 0; s < 4; ++s) Do += SA(s, mm, 0)[r2 * 8 + jj];
        int jcol = cta * 8 + jj;
        out[(size_t)b * NSTEPS * 1024 + (size_t)(NSTEPS - 1) * 1024 + jcol] = Do + lin_b[jcol];
    }
    #undef SA
    #undef SB
}

extern "C" void kernel_launch(void* const* d_in, const int* in_sizes, int n_in,
                              void* d_out, int out_size) {
    (void)in_sizes; (void)n_in; (void)out_size;
    const int*   y          = (const int*)  d_in[0];
    // d_in[1] = U (unused by the reference math)
    const float* embed      = (const float*)d_in[2];
    const float* W_ih       = (const float*)d_in[3];
    const float* W_hh       = (const float*)d_in[4];
    const float* b_ih       = (const float*)d_in[5];
    const float* b_hh       = (const float*)d_in[6];
    const float* init_state = (const float*)d_in[7];
    const float* lin_W      = (const float*)d_in[8];
    const float* lin_b      = (const float*)d_in[9];
    float* out = (float*)d_out;

    cudaFuncSetAttribute(decoder_kernel,
                         cudaFuncAttributeMaxDynamicSharedMemorySize, SMEM_TOTAL);
    decoder_kernel<<<NCTA, NTHR, SMEM_TOTAL>>>(y, embed, W_ih, W_hh, b_ih, b_hh,
                                               init_state, lin_W, lin_b, out);
}

// round 12
// speedup vs baseline: 1.1912x; 1.1912x over previous
#include <cuda_runtime.h>
#include <cuda_fp16.h>

#define NV     101          // tokens incl. start symbol (start = 100)
#define UMX    256
#define NSTEPS 257
#define NSUP   (NSTEPS + 3) // skewed superphases
#define G3     3072
#define NCTA   128
#define NTHR   512

typedef unsigned u32;

// ---------------- static device scratch (no runtime allocation) ----------------
// Fragment-packed fp16 hi/lo weights.
// g_W0p: job A (K=1024): n-rows 0..3071 = W_hh layer0 (r,z,n), 3072..4095 = lin_W.
//   [ntile(512)][ktile(64)][lane(32)] : uint4 = {Whi.b0, Whi.b1, Wlo.b0, Wlo.b1}
__device__ __align__(16) uint4 g_W0p[512 * 64 * 32];            // 16 MB
// g_W12p: layers 1,2 (K=2048): per layer n-row q*1024+j:
//   q=0:[Wih_r|Whh_r] q=1:[Wih_z|Whh_z] q=2:[Wih_n|0] q=3:[0|Whh_n]
//   [layer(2)][ntile(512)][ktile(128)][lane(32)]
__device__ __align__(16) uint4 g_W12p[2 * 512 * 128 * 32];      // 64 MB
// Fragment-packed fp16 activations: [l(3)][par(2)][mtile(4)][ktile(128)][lane(32)]
//   l=0: cols 0..1023 = h0; l=1,2: cols 0..1023 = x, 1024..2047 = h_prev
__device__ __align__(16) uint4 g_A[3 * 2 * 4 * 128 * 32];       // 1.5 MB (zero-init)
__device__ float g_T[NV * G3];          // layer0 gi table (incl b_ih0), fp32
__device__ float g_stf[3 * 64 * 1024];  // fp32 states [l][b][j]
__device__ unsigned g_bar;

// ---------------- grid barrier: release-arrive + acquire-poll ----------------
__device__ __forceinline__ void gridbar() {
    __syncthreads();
    if (threadIdx.x == 0) {
        u32 ticket;
        asm volatile("atom.add.release.gpu.global.u32 %0, [%1], 1;"
                     : "=r"(ticket) : "l"(&g_bar) : "memory");
        u32 target = ((ticket + NCTA) / NCTA) * NCTA;
        u32 cur;
        do {
            asm volatile("ld.acquire.gpu.global.u32 %0, [%1];"
                         : "=r"(cur) : "l"(&g_bar) : "memory");
        } while (cur < target);
    }
    __syncthreads();
}

__device__ __forceinline__ float sigm(float t) { return 1.0f / (1.0f + expf(-t)); }

// split fp32 -> (hi, lo) fp16 bit patterns
__device__ __forceinline__ void sph(float w, u32& hb, u32& lb) {
    __half h = __float2half_rn(w);
    hb = (u32)__half_as_ushort(h);
    lb = (u32)__half_as_ushort(__float2half_rn(w - __half2float(h)));
}
__device__ __forceinline__ uint4 pack4h(float a, float b, float c, float d) {
    u32 ah, al, bh, bl, ch, cl, dh, dl;
    sph(a, ah, al); sph(b, bh, bl); sph(c, ch, cl); sph(d, dh, dl);
    uint4 v;
    v.x = ah | (bh << 16);   // hi b0 (k0, k0+1)
    v.y = ch | (dh << 16);   // hi b1 (k0+8, k0+9)
    v.z = al | (bl << 16);   // lo b0
    v.w = cl | (dl << 16);   // lo b1
    return v;
}

// A-buffer offset (uint4 units, excluding lane)
__device__ __forceinline__ size_t aoff(int l, int par, int mt, int kt) {
    return (size_t)((((l * 2 + par) * 4 + mt) * 128 + kt)) * 32;
}
// Write activation element (b, c) as fp16 into fragment layout
__device__ __forceinline__ void storeA(int l, int par, int b, int c, float v) {
    int mt = b >> 4, mr = b & 15, kt = c >> 4, kk = c & 15;
    int lane = (mr & 7) * 4 + ((kk & 7) >> 1);
    int slot = (mr >> 3) + ((kk >> 3) << 1);
    __half* p = (__half*)(g_A + aoff(l, par, mt, kt) + lane);
    p[slot * 2 + (kk & 1)] = __float2half_rn(v);
}

// ---------------- mma.m16n8k16 fp16 ----------------
__device__ __forceinline__ void mma_f16(float* d, const uint4& a, u32 b0, u32 b1) {
    asm volatile(
        "mma.sync.aligned.m16n8k16.row.col.f32.f16.f16.f32 "
        "{%0,%1,%2,%3}, {%4,%5,%6,%7}, {%8,%9}, {%0,%1,%2,%3};"
        : "+f"(d[0]), "+f"(d[1]), "+f"(d[2]), "+f"(d[3])
        : "r"(a.x), "r"(a.y), "r"(a.z), "r"(a.w), "r"(b0), "r"(b1));
}
// 2-chain combine + store 16x8 tile into smem slab (float[128])
__device__ __forceinline__ void stD2(float* base, int rr, int cc,
                                     const float* d0, const float* d1) {
    base[rr * 8 + cc]           = d0[0] + d1[0];
    base[rr * 8 + cc + 1]       = d0[1] + d1[1];
    base[(rr + 8) * 8 + cc]     = d0[2] + d1[2];
    base[(rr + 8) * 8 + cc + 1] = d0[3] + d1[3];
}

#define SMEM_TOTAL (32768 * 4)   // 128 KB: SA 8K floats + SB1 12K + SB2 12K

// ================================================================================
__global__ void __launch_bounds__(NTHR, 1)
decoder_kernel(const int*   __restrict__ y,
               const float* __restrict__ embed,
               const float* __restrict__ W_ih,
               const float* __restrict__ W_hh,
               const float* __restrict__ b_ih,
               const float* __restrict__ b_hh,
               const float* __restrict__ init_state,
               const float* __restrict__ lin_W,
               const float* __restrict__ lin_b,
               float*       __restrict__ out)
{
    extern __shared__ float sbuf[];
    const int tid  = threadIdx.x;
    const int lane = tid & 31;
    const int wid  = tid >> 5;          // 0..15
    const int mwA  = wid & 3;           // job A: m-tile
    const int ksA  = wid >> 2;          // job A: k-slice 0..3 (16 ktiles each)
    const int mpB  = wid & 1;           // jobs L1/L2: m-half
    const int ksB  = wid >> 1;          // jobs L1/L2: k-slice 0..7 (16 ktiles each)
    const int cta  = blockIdx.x;
    const int gt   = cta * NTHR + tid;
    const int GS   = NCTA * NTHR;
    const int rr   = lane >> 2, cc = (lane & 3) << 1;

    // job A view: [s(4)][mt(4)][q(4)][128]
    #define SA(s_, mt, q) (sbuf + (((s_) * 4 + (mt)) * 4 + (q)) * 128)
    // L1/L2 views: [s(8)][mt(4)][g(3)][128]; g=2 holds i_n for s<4, h_n for s>=4
    #define SB1(s_, mt, g) (sbuf + 8192  + (((s_) * 4 + (mt)) * 3 + (g)) * 128)
    #define SB2(s_, mt, g) (sbuf + 20480 + (((s_) * 4 + (mt)) * 3 + (g)) * 128)

    // ================= PROLOGUE =================
    for (int idx = gt; idx < 512 * 64 * 32; idx += GS) {
        int ln = idx & 31, t = (idx >> 5) & 63, NT = idx >> 11;
        int n  = NT * 8 + (ln >> 2);
        int k0 = t * 16 + ((ln & 3) << 1);
        const float* src = (n < 3072) ? (W_hh + (size_t)n * 1024)
                                      : (lin_W + (size_t)(n - 3072) * 1024);
        g_W0p[idx] = pack4h(src[k0], src[k0 + 1], src[k0 + 8], src[k0 + 9]);
    }
    for (int idx = gt; idx < 2 * 512 * 128 * 32; idx += GS) {
        int ln = idx & 31, t = (idx >> 5) & 127, NT = (idx >> 12) & 511, ll = idx >> 21;
        int n  = NT * 8 + (ln >> 2);
        int qq = n >> 10, jj = n & 1023;
        int k0 = t * 16 + ((ln & 3) << 1);
        int lay = ll + 1;
        float w[4];
#pragma unroll
        for (int i = 0; i < 4; ++i) {
            int k = k0 + ((i >> 1) << 3) + (i & 1);   // k0, k0+1, k0+8, k0+9
            float v = 0.0f;
            if (qq < 2) {
                v = (k < 1024) ? W_ih[((size_t)lay * 3072 + qq * 1024 + jj) * 1024 + k]
                               : W_hh[((size_t)lay * 3072 + qq * 1024 + jj) * 1024 + k - 1024];
            } else if (qq == 2) {
                if (k < 1024) v = W_ih[((size_t)lay * 3072 + 2048 + jj) * 1024 + k];
            } else {
                if (k >= 1024) v = W_hh[((size_t)lay * 3072 + 2048 + jj) * 1024 + k - 1024];
            }
            w[i] = v;
        }
        g_W12p[idx] = pack4h(w[0], w[1], w[2], w[3]);
    }
    // fp32 token table: T[v][row] = embed[v] . W_ih0[row] + b_ih0[row]
    for (int idx = gt; idx < 3072 * 128; idx += GS) {
        int row = idx >> 7, v = idx & 127;
        if (v < NV) {
            const float* e = embed + (size_t)v * 1024;
            const float* w = W_ih + (size_t)row * 1024;
            float a0 = 0, a1 = 0, a2 = 0, a3 = 0;
            for (int k = 0; k < 1024; k += 4) {
                a0 += e[k] * w[k];         a1 += e[k + 1] * w[k + 1];
                a2 += e[k + 2] * w[k + 2]; a3 += e[k + 3] * w[k + 3];
            }
            g_T[v * G3 + row] = (a0 + a1) + (a2 + a3) + b_ih[row];
        }
    }
    // state init; parity per layer so superphase-0..2 consumers see init values:
    //   h0 read at s=0 (parity 1), h1 read at s=1 (parity 0), h2 read at s=2 (parity 1)
    for (int idx = gt; idx < 3 * 64 * 1024; idx += GS) {
        int l = idx >> 16, r = idx & 65535, b = r >> 10, j = r & 1023;
        float v = init_state[l * 1024 + j];
        g_stf[idx] = v;
        int parl = (l == 1) ? 0 : 1;
        storeA(l, parl, b, (l == 0) ? j : (1024 + j), v);
    }
    gridbar();

    // ================= SUPERPHASE LOOP =================
    // superphase s runs: layer0(s), layer1(s-1), layer2(s-2), lin(s-3)
    for (int s = 0; s < NSUP; ++s) {
        const int ps = s & 1, pr = ps ^ 1;

        // ---- job A: layer0 h-GEMM (r,z,n on h0) + lin (on h2), K=1024 ----
        {
            const int t0 = ksA * 16;
            const uint4* A0 = g_A + aoff(0, pr, mwA, t0) + lane;
            const uint4* A2 = g_A + aoff(2, pr, mwA, 64 + t0) + lane;
            const uint4* B0 = g_W0p + ((size_t)(0 * 128 + cta) * 64 + t0) * 32 + lane;
            const uint4* B1 = g_W0p + ((size_t)(1 * 128 + cta) * 64 + t0) * 32 + lane;
            const uint4* B2 = g_W0p + ((size_t)(2 * 128 + cta) * 64 + t0) * 32 + lane;
            const uint4* B3 = g_W0p + ((size_t)(3 * 128 + cta) * 64 + t0) * 32 + lane;
            float d0a[4] = {}, d0b[4] = {}, d1a[4] = {}, d1b[4] = {};
            float d2a[4] = {}, d2b[4] = {}, d3a[4] = {}, d3b[4] = {};
#pragma unroll 1
            for (int i = 0; i < 16; ++i) {
                uint4 a = A0[i * 32], c = A2[i * 32];
                uint4 b0 = B0[i * 32], b1 = B1[i * 32], b2 = B2[i * 32], b3 = B3[i * 32];
                mma_f16(d0a, a, b0.x, b0.y); mma_f16(d0b, a, b0.z, b0.w);
                mma_f16(d1a, a, b1.x, b1.y); mma_f16(d1b, a, b1.z, b1.w);
                mma_f16(d2a, a, b2.x, b2.y); mma_f16(d2b, a, b2.z, b2.w);
                mma_f16(d3a, c, b3.x, b3.y); mma_f16(d3b, c, b3.z, b3.w);
            }
            stD2(SA(ksA, mwA, 0), rr, cc, d0a, d0b);
            stD2(SA(ksA, mwA, 1), rr, cc, d1a, d1b);
            stD2(SA(ksA, mwA, 2), rr, cc, d2a, d2b);
            stD2(SA(ksA, mwA, 3), rr, cc, d3a, d3b);
        }

        // ---- jobs L1 (layer1(s-1)) and L2 (layer2(s-2)), K=2048 ----
#pragma unroll 1
        for (int l = 1; l <= 2; ++l) {
            const int t0  = ksB * 16;
            const int g2q = 2 + (ksB >> 2);        // i_n for ks<4, h_n for ks>=4
            const int mt0 = mpB * 2;
            const uint4* A  = g_A + aoff(l, pr, mt0, t0) + lane;
            const uint4* B0 = g_W12p + ((size_t)((l - 1) * 512 + 0 * 128 + cta) * 128 + t0) * 32 + lane;
            const uint4* B1 = g_W12p + ((size_t)((l - 1) * 512 + 1 * 128 + cta) * 128 + t0) * 32 + lane;
            const uint4* B2 = g_W12p + ((size_t)((l - 1) * 512 + g2q * 128 + cta) * 128 + t0) * 32 + lane;
            float m0g0a[4] = {}, m0g0b[4] = {}, m0g1a[4] = {}, m0g1b[4] = {};
            float m0g2a[4] = {}, m0g2b[4] = {};
            float m1g0a[4] = {}, m1g0b[4] = {}, m1g1a[4] = {}, m1g1b[4] = {};
            float m1g2a[4] = {}, m1g2b[4] = {};
#pragma unroll 1
            for (int i = 0; i < 16; ++i) {
                uint4 a0 = A[i * 32], a1 = A[i * 32 + 128 * 32];
                uint4 b0 = B0[i * 32], b1 = B1[i * 32], b2 = B2[i * 32];
                mma_f16(m0g0a, a0, b0.x, b0.y); mma_f16(m0g0b, a0, b0.z, b0.w);
                mma_f16(m0g1a, a0, b1.x, b1.y); mma_f16(m0g1b, a0, b1.z, b1.w);
                mma_f16(m0g2a, a0, b2.x, b2.y); mma_f16(m0g2b, a0, b2.z, b2.w);
                mma_f16(m1g0a, a1, b0.x, b0.y); mma_f16(m1g0b, a1, b0.z, b0.w);
                mma_f16(m1g1a, a1, b1.x, b1.y); mma_f16(m1g1b, a1, b1.z, b1.w);
                mma_f16(m1g2a, a1, b2.x, b2.y); mma_f16(m1g2b, a1, b2.z, b2.w);
            }
            float* s0 = (l == 1) ? SB1(ksB, mt0, 0) : SB2(ksB, mt0, 0);
            float* s1 = (l == 1) ? SB1(ksB, mt0, 1) : SB2(ksB, mt0, 1);
            float* s2 = (l == 1) ? SB1(ksB, mt0, 2) : SB2(ksB, mt0, 2);
            float* s3 = (l == 1) ? SB1(ksB, mt0 + 1, 0) : SB2(ksB, mt0 + 1, 0);
            float* s4 = (l == 1) ? SB1(ksB, mt0 + 1, 1) : SB2(ksB, mt0 + 1, 1);
            float* s5 = (l == 1) ? SB1(ksB, mt0 + 1, 2) : SB2(ksB, mt0 + 1, 2);
            stD2(s0, rr, cc, m0g0a, m0g0b);
            stD2(s1, rr, cc, m0g1a, m0g1b);
            stD2(s2, rr, cc, m0g2a, m0g2b);
            stD2(s3, rr, cc, m1g0a, m1g0b);
            stD2(s4, rr, cc, m1g1a, m1g1b);
            stD2(s5, rr, cc, m1g2a, m1g2b);
        }

        __syncthreads();

        // ---- unified epilogue: layer0(s), lin(s-3), layer1(s-1), layer2(s-2) ----
        {
            int b = tid >> 3, jj = tid & 7, mm = b >> 4, r2 = b & 15;
            int jcol = cta * 8 + jj;

            // lin(s-3)
            if (s >= 3) {
                float Do = 0;
#pragma unroll
                for (int sl = 0; sl < 4; ++sl) Do += SA(sl, mm, 3)[r2 * 8 + jj];
                out[(size_t)b * NSTEPS * 1024 + (size_t)(s - 3) * 1024 + jcol] = Do + lin_b[jcol];
            }
            // layer0(s)
            if (s < NSTEPS) {
                float Dr = 0, Dz = 0, Dn = 0;
#pragma unroll
                for (int sl = 0; sl < 4; ++sl) {
                    Dr += SA(sl, mm, 0)[r2 * 8 + jj];
                    Dz += SA(sl, mm, 1)[r2 * 8 + jj];
                    Dn += SA(sl, mm, 2)[r2 * 8 + jj];
                }
                int tok = (s == 0) ? (NV - 1) : y[b * UMX + (s - 1)];
                const float* Tv = g_T + (size_t)tok * G3;
                float r = sigm(Tv[jcol] + Dr + b_hh[jcol]);
                float z = sigm(Tv[1024 + jcol] + Dz + b_hh[1024 + jcol]);
                float n = tanhf(Tv[2048 + jcol] + r * (Dn + b_hh[2048 + jcol]));
                float hp = g_stf[b * 1024 + jcol];
                float h = (1.0f - z) * n + z * hp;
                g_stf[b * 1024 + jcol] = h;
                storeA(1, ps, b, jcol, h);   // x for layer1 (next superphase)
                storeA(0, ps, b, jcol, h);   // h0 (next superphase)
            }
            // layer1(s-1)
            if (s >= 1 && s < NSTEPS + 1) {
                float Gr = 0, Gz = 0, Gi = 0, Gh = 0;
#pragma unroll
                for (int sl = 0; sl < 8; ++sl) {
                    Gr += SB1(sl, mm, 0)[r2 * 8 + jj];
                    Gz += SB1(sl, mm, 1)[r2 * 8 + jj];
                }
#pragma unroll
                for (int sl = 0; sl < 4; ++sl) Gi += SB1(sl, mm, 2)[r2 * 8 + jj];
#pragma unroll
                for (int sl = 4; sl < 8; ++sl) Gh += SB1(sl, mm, 2)[r2 * 8 + jj];
                const float* bi  = b_ih + 1 * G3;
                const float* bhv = b_hh + 1 * G3;
                float r = sigm(Gr + bi[jcol] + bhv[jcol]);
                float z = sigm(Gz + bi[1024 + jcol] + bhv[1024 + jcol]);
                float n = tanhf(Gi + bi[2048 + jcol] + r * (Gh + bhv[2048 + jcol]));
                float hp = g_stf[(1 * 64 + b) * 1024 + jcol];
                float h = (1.0f - z) * n + z * hp;
                g_stf[(1 * 64 + b) * 1024 + jcol] = h;
                storeA(2, ps, b, jcol, h);          // x for layer2 (next superphase)
                storeA(1, ps, b, 1024 + jcol, h);   // h1 (next superphase)
            }
            // layer2(s-2)
            if (s >= 2 && s < NSTEPS + 2) {
                float Gr = 0, Gz = 0, Gi = 0, Gh = 0;
#pragma unroll
                for (int sl = 0; sl < 8; ++sl) {
                    Gr += SB2(sl, mm, 0)[r2 * 8 + jj];
                    Gz += SB2(sl, mm, 1)[r2 * 8 + jj];
                }
#pragma unroll
                for (int sl = 0; sl < 4; ++sl) Gi += SB2(sl, mm, 2)[r2 * 8 + jj];
#pragma unroll
                for (int sl = 4; sl < 8; ++sl) Gh += SB2(sl, mm, 2)[r2 * 8 + jj];
                const float* bi  = b_ih + 2 * G3;
                const float* bhv = b_hh + 2 * G3;
                float r = sigm(Gr + bi[jcol] + bhv[jcol]);
                float z = sigm(Gz + bi[1024 + jcol] + bhv[1024 + jcol]);
                float n = tanhf(Gi + bi[2048 + jcol] + r * (Gh + bhv[2048 + jcol]));
                float hp = g_stf[(2 * 64 + b) * 1024 + jcol];
                float h = (1.0f - z) * n + z * hp;
                g_stf[(2 * 64 + b) * 1024 + jcol] = h;
                storeA(2, ps, b, 1024 + jcol, h);   // h2: layer2 + lin (next superphase)
            }
        }
        gridbar();
    }
    #undef SA
    #undef SB1
    #undef SB2
}

extern "C" void kernel_launch(void* const* d_in, const int* in_sizes, int n_in,
                              void* d_out, int out_size) {
    (void)in_sizes; (void)n_in; (void)out_size;
    const int*   y          = (const int*)  d_in[0];
    // d_in[1] = U (unused by the reference math)
    const float* embed      = (const float*)d_in[2];
    const float* W_ih       = (const float*)d_in[3];
    const float* W_hh       = (const float*)d_in[4];
    const float* b_ih       = (const float*)d_in[5];
    const float* b_hh       = (const float*)d_in[6];
    const float* init_state = (const float*)d_in[7];
    const float* lin_W      = (const float*)d_in[8];
    const float* lin_b      = (const float*)d_in[9];
    float* out = (float*)d_out;

    cudaFuncSetAttribute(decoder_kernel,
                         cudaFuncAttributeMaxDynamicSharedMemorySize, SMEM_TOTAL);
    decoder_kernel<<<NCTA, NTHR, SMEM_TOTAL>>>(y, embed, W_ih, W_hh, b_ih, b_hh,
                                               init_state, lin_W, lin_b, out);
}

// round 13
// speedup vs baseline: 1.2730x; 1.0687x over previous
#include <cuda_runtime.h>
#include <cuda_fp16.h>

#define NV     101          // tokens incl. start symbol (start = 100)
#define UMX    256
#define NSTEPS 257
#define NSUP   (NSTEPS + 3) // skewed superphases
#define G3     3072
#define NCTA   128
#define NTHR   512

typedef unsigned u32;

// ---------------- static device scratch (no runtime allocation) ----------------
// Fragment-packed fp16 weights (single plane, no lo chain).
// g_W0p: job A (K=1024): n-rows 0..3071 = W_hh layer0 (r,z,n), 3072..4095 = lin_W.
//   [ntile(512)][ktile(64)][lane(32)] : uint2 = {W.b0, W.b1}
__device__ __align__(16) uint2 g_W0p[512 * 64 * 32];            // 8 MB
// g_W12p: layers 1,2 (K=2048): per layer n-row q*1024+j:
//   q=0:[Wih_r|Whh_r] q=1:[Wih_z|Whh_z] q=2:[Wih_n|0] q=3:[0|Whh_n]
//   [layer(2)][ntile(512)][ktile(128)][lane(32)]
__device__ __align__(16) uint2 g_W12p[2 * 512 * 128 * 32];      // 32 MB
// Fragment-packed fp16 activations: [l(3)][par(2)][mtile(4)][ktile(128)][lane(32)]
//   l=0: cols 0..1023 = h0; l=1,2: cols 0..1023 = x, 1024..2047 = h_prev
__device__ __align__(16) uint4 g_A[3 * 2 * 4 * 128 * 32];       // 1.5 MB
__device__ float g_T[NV * G3];          // layer0 gi table (incl b_ih0), fp32
__device__ float g_stf[3 * 64 * 1024];  // fp32 states [l][b][j]
__device__ unsigned g_bar;

// ---------------- grid barrier: release-arrive + acquire-poll ----------------
__device__ __forceinline__ void gridbar() {
    __syncthreads();
    if (threadIdx.x == 0) {
        u32 ticket;
        asm volatile("atom.add.release.gpu.global.u32 %0, [%1], 1;"
                     : "=r"(ticket) : "l"(&g_bar) : "memory");
        u32 target = ((ticket + NCTA) / NCTA) * NCTA;
        u32 cur;
        do {
            asm volatile("ld.acquire.gpu.global.u32 %0, [%1];"
                         : "=r"(cur) : "l"(&g_bar) : "memory");
        } while (cur < target);
    }
    __syncthreads();
}

__device__ __forceinline__ float sigm(float t) { return 1.0f / (1.0f + expf(-t)); }

__device__ __forceinline__ u32 hbits(float w) {
    return (u32)__half_as_ushort(__float2half_rn(w));
}
__device__ __forceinline__ uint2 pack2h(float a, float b, float c, float d) {
    uint2 v;
    v.x = hbits(a) | (hbits(b) << 16);   // b0 (k0, k0+1)
    v.y = hbits(c) | (hbits(d) << 16);   // b1 (k0+8, k0+9)
    return v;
}

// A-buffer offset (uint4 units, excluding lane)
__device__ __forceinline__ size_t aoff(int l, int par, int mt, int kt) {
    return (size_t)((((l * 2 + par) * 4 + mt) * 128 + kt)) * 32;
}
// Write activation element (b, c) as fp16 into fragment layout
__device__ __forceinline__ void storeA(int l, int par, int b, int c, float v) {
    int mt = b >> 4, mr = b & 15, kt = c >> 4, kk = c & 15;
    int lane = (mr & 7) * 4 + ((kk & 7) >> 1);
    int slot = (mr >> 3) + ((kk >> 3) << 1);
    __half* p = (__half*)(g_A + aoff(l, par, mt, kt) + lane);
    p[slot * 2 + (kk & 1)] = __float2half_rn(v);
}

// ---------------- mma.m16n8k16 fp16 ----------------
__device__ __forceinline__ void mma_f16(float* d, const uint4& a, u32 b0, u32 b1) {
    asm volatile(
        "mma.sync.aligned.m16n8k16.row.col.f32.f16.f16.f32 "
        "{%0,%1,%2,%3}, {%4,%5,%6,%7}, {%8,%9}, {%0,%1,%2,%3};"
        : "+f"(d[0]), "+f"(d[1]), "+f"(d[2]), "+f"(d[3])
        : "r"(a.x), "r"(a.y), "r"(a.z), "r"(a.w), "r"(b0), "r"(b1));
}
// store a 16x8 tile into smem slab (float[128])
__device__ __forceinline__ void stD1(float* base, int rr, int cc, const float* d) {
    base[rr * 8 + cc]           = d[0];
    base[rr * 8 + cc + 1]       = d[1];
    base[(rr + 8) * 8 + cc]     = d[2];
    base[(rr + 8) * 8 + cc + 1] = d[3];
}

#define SMEM_TOTAL (32768 * 4)   // 128 KB: SA 8K floats + SB1 12K + SB2 12K

// ================================================================================
__global__ void __launch_bounds__(NTHR, 1)
decoder_kernel(const int*   __restrict__ y,
               const float* __restrict__ embed,
               const float* __restrict__ W_ih,
               const float* __restrict__ W_hh,
               const float* __restrict__ b_ih,
               const float* __restrict__ b_hh,
               const float* __restrict__ init_state,
               const float* __restrict__ lin_W,
               const float* __restrict__ lin_b,
               float*       __restrict__ out)
{
    extern __shared__ float sbuf[];
    const int tid  = threadIdx.x;
    const int lane = tid & 31;
    const int wid  = tid >> 5;          // 0..15
    const int mwA  = wid & 3;           // job A: m-tile
    const int ksA  = wid >> 2;          // job A: k-slice 0..3 (16 ktiles each)
    const int mpB  = wid & 1;           // jobs L1/L2: m-half
    const int ksB  = wid >> 1;          // jobs L1/L2: k-slice 0..7 (16 ktiles each)
    const int cta  = blockIdx.x;
    const int gt   = cta * NTHR + tid;
    const int GS   = NCTA * NTHR;
    const int rr   = lane >> 2, cc = (lane & 3) << 1;

    // job A view: [s(4)][mt(4)][q(4)][128]
    #define SA(s_, mt, q) (sbuf + (((s_) * 4 + (mt)) * 4 + (q)) * 128)
    // L1/L2 views: [s(8)][mt(4)][g(3)][128]; g=2 holds i_n for s<4, h_n for s>=4
    #define SB1(s_, mt, g) (sbuf + 8192  + (((s_) * 4 + (mt)) * 3 + (g)) * 128)
    #define SB2(s_, mt, g) (sbuf + 20480 + (((s_) * 4 + (mt)) * 3 + (g)) * 128)

    // ================= PROLOGUE =================
    for (int idx = gt; idx < 512 * 64 * 32; idx += GS) {
        int ln = idx & 31, t = (idx >> 5) & 63, NT = idx >> 11;
        int n  = NT * 8 + (ln >> 2);
        int k0 = t * 16 + ((ln & 3) << 1);
        const float* src = (n < 3072) ? (W_hh + (size_t)n * 1024)
                                      : (lin_W + (size_t)(n - 3072) * 1024);
        g_W0p[idx] = pack2h(src[k0], src[k0 + 1], src[k0 + 8], src[k0 + 9]);
    }
    for (int idx = gt; idx < 2 * 512 * 128 * 32; idx += GS) {
        int ln = idx & 31, t = (idx >> 5) & 127, NT = (idx >> 12) & 511, ll = idx >> 21;
        int n  = NT * 8 + (ln >> 2);
        int qq = n >> 10, jj = n & 1023;
        int k0 = t * 16 + ((ln & 3) << 1);
        int lay = ll + 1;
        float w[4];
#pragma unroll
        for (int i = 0; i < 4; ++i) {
            int k = k0 + ((i >> 1) << 3) + (i & 1);   // k0, k0+1, k0+8, k0+9
            float v = 0.0f;
            if (qq < 2) {
                v = (k < 1024) ? W_ih[((size_t)lay * 3072 + qq * 1024 + jj) * 1024 + k]
                               : W_hh[((size_t)lay * 3072 + qq * 1024 + jj) * 1024 + k - 1024];
            } else if (qq == 2) {
                if (k < 1024) v = W_ih[((size_t)lay * 3072 + 2048 + jj) * 1024 + k];
            } else {
                if (k >= 1024) v = W_hh[((size_t)lay * 3072 + 2048 + jj) * 1024 + k - 1024];
            }
            w[i] = v;
        }
        g_W12p[idx] = pack2h(w[0], w[1], w[2], w[3]);
    }
    // fp32 token table: T[v][row] = embed[v] . W_ih0[row] + b_ih0[row]
    for (int idx = gt; idx < 3072 * 128; idx += GS) {
        int row = idx >> 7, v = idx & 127;
        if (v < NV) {
            const float* e = embed + (size_t)v * 1024;
            const float* w = W_ih + (size_t)row * 1024;
            float a0 = 0, a1 = 0, a2 = 0, a3 = 0;
            for (int k = 0; k < 1024; k += 4) {
                a0 += e[k] * w[k];         a1 += e[k + 1] * w[k + 1];
                a2 += e[k + 2] * w[k + 2]; a3 += e[k + 3] * w[k + 3];
            }
            g_T[v * G3 + row] = (a0 + a1) + (a2 + a3) + b_ih[row];
        }
    }
    // state init; parity per layer so superphase-0..2 consumers see init values:
    //   h0 read at s=0 (parity 1), h1 read at s=1 (parity 0), h2 read at s=2 (parity 1)
    for (int idx = gt; idx < 3 * 64 * 1024; idx += GS) {
        int l = idx >> 16, r = idx & 65535, b = r >> 10, j = r & 1023;
        float v = init_state[l * 1024 + j];
        g_stf[idx] = v;
        int parl = (l == 1) ? 0 : 1;
        storeA(l, parl, b, (l == 0) ? j : (1024 + j), v);
    }
    gridbar();

    // ================= SUPERPHASE LOOP =================
    // superphase s runs: layer0(s), layer1(s-1), layer2(s-2), lin(s-3)
    for (int s = 0; s < NSUP; ++s) {
        const int ps = s & 1, pr = ps ^ 1;

        // ---- job A: layer0 h-GEMM (r,z,n on h0) + lin (on h2), K=1024 ----
        {
            const int t0 = ksA * 16;
            const uint4* A0 = g_A + aoff(0, pr, mwA, t0) + lane;
            const uint4* A2 = g_A + aoff(2, pr, mwA, 64 + t0) + lane;
            const uint2* B0 = g_W0p + ((size_t)(0 * 128 + cta) * 64 + t0) * 32 + lane;
            const uint2* B1 = g_W0p + ((size_t)(1 * 128 + cta) * 64 + t0) * 32 + lane;
            const uint2* B2 = g_W0p + ((size_t)(2 * 128 + cta) * 64 + t0) * 32 + lane;
            const uint2* B3 = g_W0p + ((size_t)(3 * 128 + cta) * 64 + t0) * 32 + lane;
            float d0[4] = {}, d1[4] = {}, d2[4] = {}, d3[4] = {};
#pragma unroll 1
            for (int i = 0; i < 16; ++i) {
                uint4 a = A0[i * 32], c = A2[i * 32];
                uint2 b0 = B0[i * 32], b1 = B1[i * 32], b2 = B2[i * 32], b3 = B3[i * 32];
                mma_f16(d0, a, b0.x, b0.y);
                mma_f16(d1, a, b1.x, b1.y);
                mma_f16(d2, a, b2.x, b2.y);
                mma_f16(d3, c, b3.x, b3.y);
            }
            stD1(SA(ksA, mwA, 0), rr, cc, d0);
            stD1(SA(ksA, mwA, 1), rr, cc, d1);
            stD1(SA(ksA, mwA, 2), rr, cc, d2);
            stD1(SA(ksA, mwA, 3), rr, cc, d3);
        }

        // ---- jobs L1 (layer1(s-1)) and L2 (layer2(s-2)), K=2048 ----
#pragma unroll 1
        for (int l = 1; l <= 2; ++l) {
            const int t0  = ksB * 16;
            const int g2q = 2 + (ksB >> 2);        // i_n for ks<4, h_n for ks>=4
            const int mt0 = mpB * 2;
            const uint4* A  = g_A + aoff(l, pr, mt0, t0) + lane;
            const uint2* B0 = g_W12p + ((size_t)((l - 1) * 512 + 0 * 128 + cta) * 128 + t0) * 32 + lane;
            const uint2* B1 = g_W12p + ((size_t)((l - 1) * 512 + 1 * 128 + cta) * 128 + t0) * 32 + lane;
            const uint2* B2 = g_W12p + ((size_t)((l - 1) * 512 + g2q * 128 + cta) * 128 + t0) * 32 + lane;
            float m0g0[4] = {}, m0g1[4] = {}, m0g2[4] = {};
            float m1g0[4] = {}, m1g1[4] = {}, m1g2[4] = {};
#pragma unroll 1
            for (int i = 0; i < 16; ++i) {
                uint4 a0 = A[i * 32], a1 = A[i * 32 + 128 * 32];
                uint2 b0 = B0[i * 32], b1 = B1[i * 32], b2 = B2[i * 32];
                mma_f16(m0g0, a0, b0.x, b0.y);
                mma_f16(m0g1, a0, b1.x, b1.y);
                mma_f16(m0g2, a0, b2.x, b2.y);
                mma_f16(m1g0, a1, b0.x, b0.y);
                mma_f16(m1g1, a1, b1.x, b1.y);
                mma_f16(m1g2, a1, b2.x, b2.y);
            }
            float* s0 = (l == 1) ? SB1(ksB, mt0, 0) : SB2(ksB, mt0, 0);
            float* s1 = (l == 1) ? SB1(ksB, mt0, 1) : SB2(ksB, mt0, 1);
            float* s2 = (l == 1) ? SB1(ksB, mt0, 2) : SB2(ksB, mt0, 2);
            float* s3 = (l == 1) ? SB1(ksB, mt0 + 1, 0) : SB2(ksB, mt0 + 1, 0);
            float* s4 = (l == 1) ? SB1(ksB, mt0 + 1, 1) : SB2(ksB, mt0 + 1, 1);
            float* s5 = (l == 1) ? SB1(ksB, mt0 + 1, 2) : SB2(ksB, mt0 + 1, 2);
            stD1(s0, rr, cc, m0g0);
            stD1(s1, rr, cc, m0g1);
            stD1(s2, rr, cc, m0g2);
            stD1(s3, rr, cc, m1g0);
            stD1(s4, rr, cc, m1g1);
            stD1(s5, rr, cc, m1g2);
        }

        __syncthreads();

        // ---- unified epilogue: layer0(s), lin(s-3), layer1(s-1), layer2(s-2) ----
        {
            int b = tid >> 3, jj = tid & 7, mm = b >> 4, r2 = b & 15;
            int jcol = cta * 8 + jj;

            // lin(s-3)
            if (s >= 3) {
                float Do = 0;
#pragma unroll
                for (int sl = 0; sl < 4; ++sl) Do += SA(sl, mm, 3)[r2 * 8 + jj];
                out[(size_t)b * NSTEPS * 1024 + (size_t)(s - 3) * 1024 + jcol] = Do + lin_b[jcol];
            }
            // layer0(s)
            if (s < NSTEPS) {
                float Dr = 0, Dz = 0, Dn = 0;
#pragma unroll
                for (int sl = 0; sl < 4; ++sl) {
                    Dr += SA(sl, mm, 0)[r2 * 8 + jj];
                    Dz += SA(sl, mm, 1)[r2 * 8 + jj];
                    Dn += SA(sl, mm, 2)[r2 * 8 + jj];
                }
                int tok = (s == 0) ? (NV - 1) : y[b * UMX + (s - 1)];
                const float* Tv = g_T + (size_t)tok * G3;
                float r = sigm(Tv[jcol] + Dr + b_hh[jcol]);
                float z = sigm(Tv[1024 + jcol] + Dz + b_hh[1024 + jcol]);
                float n = tanhf(Tv[2048 + jcol] + r * (Dn + b_hh[2048 + jcol]));
                float hp = g_stf[b * 1024 + jcol];
                float h = (1.0f - z) * n + z * hp;
                g_stf[b * 1024 + jcol] = h;
                storeA(1, ps, b, jcol, h);   // x for layer1 (next superphase)
                storeA(0, ps, b, jcol, h);   // h0 (next superphase)
            }
            // layer1(s-1)
            if (s >= 1 && s < NSTEPS + 1) {
                float Gr = 0, Gz = 0, Gi = 0, Gh = 0;
#pragma unroll
                for (int sl = 0; sl < 8; ++sl) {
                    Gr += SB1(sl, mm, 0)[r2 * 8 + jj];
                    Gz += SB1(sl, mm, 1)[r2 * 8 + jj];
                }
#pragma unroll
                for (int sl = 0; sl < 4; ++sl) Gi += SB1(sl, mm, 2)[r2 * 8 + jj];
#pragma unroll
                for (int sl = 4; sl < 8; ++sl) Gh += SB1(sl, mm, 2)[r2 * 8 + jj];
                const float* bi  = b_ih + 1 * G3;
                const float* bhv = b_hh + 1 * G3;
                float r = sigm(Gr + bi[jcol] + bhv[jcol]);
                float z = sigm(Gz + bi[1024 + jcol] + bhv[1024 + jcol]);
                float n = tanhf(Gi + bi[2048 + jcol] + r * (Gh + bhv[2048 + jcol]));
                float hp = g_stf[(1 * 64 + b) * 1024 + jcol];
                float h = (1.0f - z) * n + z * hp;
                g_stf[(1 * 64 + b) * 1024 + jcol] = h;
                storeA(2, ps, b, jcol, h);          // x for layer2 (next superphase)
                storeA(1, ps, b, 1024 + jcol, h);   // h1 (next superphase)
            }
            // layer2(s-2)
            if (s >= 2 && s < NSTEPS + 2) {
                float Gr = 0, Gz = 0, Gi = 0, Gh = 0;
#pragma unroll
                for (int sl = 0; sl < 8; ++sl) {
                    Gr += SB2(sl, mm, 0)[r2 * 8 + jj];
                    Gz += SB2(sl, mm, 1)[r2 * 8 + jj];
                }
#pragma unroll
                for (int sl = 0; sl < 4; ++sl) Gi += SB2(sl, mm, 2)[r2 * 8 + jj];
#pragma unroll
                for (int sl = 4; sl < 8; ++sl) Gh += SB2(sl, mm, 2)[r2 * 8 + jj];
                const float* bi  = b_ih + 2 * G3;
                const float* bhv = b_hh + 2 * G3;
                float r = sigm(Gr + bi[jcol] + bhv[jcol]);
                float z = sigm(Gz + bi[1024 + jcol] + bhv[1024 + jcol]);
                float n = tanhf(Gi + bi[2048 + jcol] + r * (Gh + bhv[2048 + jcol]));
                float hp = g_stf[(2 * 64 + b) * 1024 + jcol];
                float h = (1.0f - z) * n + z * hp;
                g_stf[(2 * 64 + b) * 1024 + jcol] = h;
                storeA(2, ps, b, 1024 + jcol, h);   // h2: layer2 + lin (next superphase)
            }
        }
        gridbar();
    }
    #undef SA
    #undef SB1
    #undef SB2
}

extern "C" void kernel_launch(void* const* d_in, const int* in_sizes, int n_in,
                              void* d_out, int out_size) {
    (void)in_sizes; (void)n_in; (void)out_size;
    const int*   y          = (const int*)  d_in[0];
    // d_in[1] = U (unused by the reference math)
    const float* embed      = (const float*)d_in[2];
    const float* W_ih       = (const float*)d_in[3];
    const float* W_hh       = (const float*)d_in[4];
    const float* b_ih       = (const float*)d_in[5];
    const float* b_hh       = (const float*)d_in[6];
    const float* init_state = (const float*)d_in[7];
    const float* lin_W      = (const float*)d_in[8];
    const float* lin_b      = (const float*)d_in[9];
    float* out = (float*)d_out;

    cudaFuncSetAttribute(decoder_kernel,
                         cudaFuncAttributeMaxDynamicSharedMemorySize, SMEM_TOTAL);
    decoder_kernel<<<NCTA, NTHR, SMEM_TOTAL>>>(y, embed, W_ih, W_hh, b_ih, b_hh,
                                               init_state, lin_W, lin_b, out);
}

// round 14
// speedup vs baseline: 1.3337x; 1.0477x over previous
#include <cuda_runtime.h>
#include <cuda_fp16.h>

#define NV     101          // tokens incl. start symbol (start = 100)
#define UMX    256
#define NSTEPS 257
#define NSUP   (NSTEPS + 3) // skewed superphases
#define G3     3072
#define NCTA   128
#define NTHR   512

typedef unsigned u32;

// ---------------- static device scratch (no runtime allocation) ----------------
// Fragment-packed fp16 weights (single plane).
// g_W0p: job A (K=1024): n-rows 0..3071 = W_hh layer0 (r,z,n), 3072..4095 = lin_W.
//   [ntile(512)][ktile(64)][lane(32)] : uint2 = {W.b0, W.b1}
__device__ __align__(16) uint2 g_W0p[512 * 64 * 32];            // 8 MB
// g_W12p: layers 1,2 (K=2048): per layer n-row q*1024+j:
//   q=0:[Wih_r|Whh_r] q=1:[Wih_z|Whh_z] q=2:[Wih_n|0] q=3:[0|Whh_n]
//   [layer(2)][ntile(512)][ktile(128)][lane(32)]
__device__ __align__(16) uint2 g_W12p[2 * 512 * 128 * 32];      // 32 MB
// Fragment-packed fp16 activations: [l(3)][par(2)][mtile(4)][ktile(128)][lane(32)]
//   l=0: cols 0..1023 = h0; l=1,2: cols 0..1023 = x, 1024..2047 = h_prev
__device__ __align__(16) uint4 g_A[3 * 2 * 4 * 128 * 32];       // 1.5 MB
__device__ float g_T[NV * G3];          // layer0 gi table (incl b_ih0), fp32
__device__ unsigned g_bar;

// ---------------- grid barrier: release-arrive + acquire-poll ----------------
__device__ __forceinline__ void gridbar() {
    __syncthreads();
    if (threadIdx.x == 0) {
        u32 ticket;
        asm volatile("atom.add.release.gpu.global.u32 %0, [%1], 1;"
                     : "=r"(ticket) : "l"(&g_bar) : "memory");
        u32 target = ((ticket + NCTA) / NCTA) * NCTA;
        u32 cur;
        do {
            asm volatile("ld.acquire.gpu.global.u32 %0, [%1];"
                         : "=r"(cur) : "l"(&g_bar) : "memory");
        } while (cur < target);
    }
    __syncthreads();
}

__device__ __forceinline__ float sigm(float t) { return 1.0f / (1.0f + expf(-t)); }

__device__ __forceinline__ u32 hbits(float w) {
    return (u32)__half_as_ushort(__float2half_rn(w));
}
__device__ __forceinline__ uint2 pack2h(float a, float b, float c, float d) {
    uint2 v;
    v.x = hbits(a) | (hbits(b) << 16);   // b0 (k0, k0+1)
    v.y = hbits(c) | (hbits(d) << 16);   // b1 (k0+8, k0+9)
    return v;
}

// A-buffer offset (uint4 units, excluding lane)
__device__ __forceinline__ size_t aoff(int l, int par, int mt, int kt) {
    return (size_t)((((l * 2 + par) * 4 + mt) * 128 + kt)) * 32;
}
// Write activation element (b, c) as fp16 into fragment layout
__device__ __forceinline__ void storeA(int l, int par, int b, int c, float v) {
    int mt = b >> 4, mr = b & 15, kt = c >> 4, kk = c & 15;
    int lane = (mr & 7) * 4 + ((kk & 7) >> 1);
    int slot = (mr >> 3) + ((kk >> 3) << 1);
    __half* p = (__half*)(g_A + aoff(l, par, mt, kt) + lane);
    p[slot * 2 + (kk & 1)] = __float2half_rn(v);
}

// ---------------- mma.m16n8k16 fp16 ----------------
__device__ __forceinline__ void mma_f16(float* d, const uint4& a, u32 b0, u32 b1) {
    asm volatile(
        "mma.sync.aligned.m16n8k16.row.col.f32.f16.f16.f32 "
        "{%0,%1,%2,%3}, {%4,%5,%6,%7}, {%8,%9}, {%0,%1,%2,%3};"
        : "+f"(d[0]), "+f"(d[1]), "+f"(d[2]), "+f"(d[3])
        : "r"(a.x), "r"(a.y), "r"(a.z), "r"(a.w), "r"(b0), "r"(b1));
}
// store a 16x8 tile into smem slab (float[128])
__device__ __forceinline__ void stD1(float* base, int rr, int cc, const float* d) {
    base[rr * 8 + cc]           = d[0];
    base[rr * 8 + cc + 1]       = d[1];
    base[(rr + 8) * 8 + cc]     = d[2];
    base[(rr + 8) * 8 + cc + 1] = d[3];
}

#define SMEM_TOTAL (32768 * 4)   // 128 KB: SA 8K floats + SB1 12K + SB2 12K

// ================================================================================
__global__ void __launch_bounds__(NTHR, 1)
decoder_kernel(const int*   __restrict__ y,
               const float* __restrict__ embed,
               const float* __restrict__ W_ih,
               const float* __restrict__ W_hh,
               const float* __restrict__ b_ih,
               const float* __restrict__ b_hh,
               const float* __restrict__ init_state,
               const float* __restrict__ lin_W,
               const float* __restrict__ lin_b,
               float*       __restrict__ out)
{
    extern __shared__ float sbuf[];
    const int tid  = threadIdx.x;
    const int lane = tid & 31;
    const int wid  = tid >> 5;          // 0..15
    const int mwA  = wid & 3;           // job A: m-tile
    const int ksA  = wid >> 2;          // job A: k-slice 0..3 (16 ktiles each)
    const int mpB  = wid & 1;           // jobs L1/L2: m-half
    const int ksB  = wid >> 1;          // jobs L1/L2: k-slice 0..7 (16 ktiles each)
    const int cta  = blockIdx.x;
    const int gt   = cta * NTHR + tid;
    const int GS   = NCTA * NTHR;
    const int rr   = lane >> 2, cc = (lane & 3) << 1;

    // epilogue element owned by this thread
    const int eb   = tid >> 3;          // batch 0..63
    const int ejj  = tid & 7;
    const int emm  = eb >> 4, er2 = eb & 15;
    const int jcol = cta * 8 + ejj;

    // job A view: [s(4)][mt(4)][q(4)][128]
    #define SA(s_, mt, q) (sbuf + (((s_) * 4 + (mt)) * 4 + (q)) * 128)
    // L1/L2 views: [s(8)][mt(4)][g(3)][128]; g=2 holds i_n for s<4, h_n for s>=4
    #define SB1(s_, mt, g) (sbuf + 8192  + (((s_) * 4 + (mt)) * 3 + (g)) * 128)
    #define SB2(s_, mt, g) (sbuf + 20480 + (((s_) * 4 + (mt)) * 3 + (g)) * 128)

    // ================= PROLOGUE =================
    for (int idx = gt; idx < 512 * 64 * 32; idx += GS) {
        int ln = idx & 31, t = (idx >> 5) & 63, NT = idx >> 11;
        int n  = NT * 8 + (ln >> 2);
        int k0 = t * 16 + ((ln & 3) << 1);
        const float* src = (n < 3072) ? (W_hh + (size_t)n * 1024)
                                      : (lin_W + (size_t)(n - 3072) * 1024);
        g_W0p[idx] = pack2h(src[k0], src[k0 + 1], src[k0 + 8], src[k0 + 9]);
    }
    for (int idx = gt; idx < 2 * 512 * 128 * 32; idx += GS) {
        int ln = idx & 31, t = (idx >> 5) & 127, NT = (idx >> 12) & 511, ll = idx >> 21;
        int n  = NT * 8 + (ln >> 2);
        int qq = n >> 10, jj = n & 1023;
        int k0 = t * 16 + ((ln & 3) << 1);
        int lay = ll + 1;
        float w[4];
#pragma unroll
        for (int i = 0; i < 4; ++i) {
            int k = k0 + ((i >> 1) << 3) + (i & 1);   // k0, k0+1, k0+8, k0+9
            float v = 0.0f;
            if (qq < 2) {
                v = (k < 1024) ? W_ih[((size_t)lay * 3072 + qq * 1024 + jj) * 1024 + k]
                               : W_hh[((size_t)lay * 3072 + qq * 1024 + jj) * 1024 + k - 1024];
            } else if (qq == 2) {
                if (k < 1024) v = W_ih[((size_t)lay * 3072 + 2048 + jj) * 1024 + k];
            } else {
                if (k >= 1024) v = W_hh[((size_t)lay * 3072 + 2048 + jj) * 1024 + k - 1024];
            }
            w[i] = v;
        }
        g_W12p[idx] = pack2h(w[0], w[1], w[2], w[3]);
    }
    // fp32 token table: T[v][row] = embed[v] . W_ih0[row] + b_ih0[row]
    for (int idx = gt; idx < 3072 * 128; idx += GS) {
        int row = idx >> 7, v = idx & 127;
        if (v < NV) {
            const float* e = embed + (size_t)v * 1024;
            const float* w = W_ih + (size_t)row * 1024;
            float a0 = 0, a1 = 0, a2 = 0, a3 = 0;
            for (int k = 0; k < 1024; k += 4) {
                a0 += e[k] * w[k];         a1 += e[k + 1] * w[k + 1];
                a2 += e[k + 2] * w[k + 2]; a3 += e[k + 3] * w[k + 3];
            }
            g_T[v * G3 + row] = (a0 + a1) + (a2 + a3) + b_ih[row];
        }
    }
    // activation init; parity so superphase-0..2 consumers see init values:
    //   h0 read at s=0 (parity 1), h1 read at s=1 (parity 0), h2 read at s=2 (parity 1)
    for (int idx = gt; idx < 3 * 64 * 1024; idx += GS) {
        int l = idx >> 16, r = idx & 65535, b = r >> 10, j = r & 1023;
        float v = init_state[l * 1024 + j];
        int parl = (l == 1) ? 0 : 1;
        storeA(l, parl, b, (l == 0) ? j : (1024 + j), v);
    }

    // ---- per-thread register state + hoisted biases ----
    float h0s = init_state[jcol];
    float h1s = init_state[1024 + jcol];
    float h2s = init_state[2048 + jcol];
    const float bh0r = b_hh[jcol], bh0z = b_hh[1024 + jcol], bh0n = b_hh[2048 + jcol];
    const float bi1r = b_ih[G3 + jcol], bi1z = b_ih[G3 + 1024 + jcol], bi1n = b_ih[G3 + 2048 + jcol];
    const float bh1r = b_hh[G3 + jcol], bh1z = b_hh[G3 + 1024 + jcol], bh1n = b_hh[G3 + 2048 + jcol];
    const float bi2r = b_ih[2 * G3 + jcol], bi2z = b_ih[2 * G3 + 1024 + jcol], bi2n = b_ih[2 * G3 + 2048 + jcol];
    const float bh2r = b_hh[2 * G3 + jcol], bh2z = b_hh[2 * G3 + 1024 + jcol], bh2n = b_hh[2 * G3 + 2048 + jcol];
    const float lb   = lin_b[jcol];

    gridbar();

    // ================= SUPERPHASE LOOP =================
    // superphase s runs: layer0(s), layer1(s-1), layer2(s-2), lin(s-3)
    for (int s = 0; s < NSUP; ++s) {
        const int ps = s & 1, pr = ps ^ 1;

        // ---- prefetch token-table row for layer0(s) (hidden under the GEMMs) ----
        float tv0 = 0.0f, tv1 = 0.0f, tv2 = 0.0f;
        if (s < NSTEPS) {
            int tok = (s == 0) ? (NV - 1) : y[eb * UMX + (s - 1)];
            const float* Tv = g_T + (size_t)tok * G3;
            tv0 = Tv[jcol]; tv1 = Tv[1024 + jcol]; tv2 = Tv[2048 + jcol];
        }

        // ---- job A: layer0 h-GEMM (r,z,n on h0) + lin (on h2), K=1024 ----
        {
            const int t0 = ksA * 16;
            const uint4* A0 = g_A + aoff(0, pr, mwA, t0) + lane;
            const uint4* A2 = g_A + aoff(2, pr, mwA, 64 + t0) + lane;
            const uint2* B0 = g_W0p + ((size_t)(0 * 128 + cta) * 64 + t0) * 32 + lane;
            const uint2* B1 = g_W0p + ((size_t)(1 * 128 + cta) * 64 + t0) * 32 + lane;
            const uint2* B2 = g_W0p + ((size_t)(2 * 128 + cta) * 64 + t0) * 32 + lane;
            const uint2* B3 = g_W0p + ((size_t)(3 * 128 + cta) * 64 + t0) * 32 + lane;
            float d0[4] = {}, d1[4] = {}, d2[4] = {}, d3[4] = {};
#pragma unroll 1
            for (int i = 0; i < 16; ++i) {
                uint4 a = A0[i * 32], c = A2[i * 32];
                uint2 b0 = B0[i * 32], b1 = B1[i * 32], b2 = B2[i * 32], b3 = B3[i * 32];
                mma_f16(d0, a, b0.x, b0.y);
                mma_f16(d1, a, b1.x, b1.y);
                mma_f16(d2, a, b2.x, b2.y);
                mma_f16(d3, c, b3.x, b3.y);
            }
            stD1(SA(ksA, mwA, 0), rr, cc, d0);
            stD1(SA(ksA, mwA, 1), rr, cc, d1);
            stD1(SA(ksA, mwA, 2), rr, cc, d2);
            stD1(SA(ksA, mwA, 3), rr, cc, d3);
        }

        // ---- jobs L1 (layer1(s-1)) and L2 (layer2(s-2)), K=2048 ----
#pragma unroll 1
        for (int l = 1; l <= 2; ++l) {
            const int t0  = ksB * 16;
            const int g2q = 2 + (ksB >> 2);        // i_n for ks<4, h_n for ks>=4
            const int mt0 = mpB * 2;
            const uint4* A  = g_A + aoff(l, pr, mt0, t0) + lane;
            const uint2* B0 = g_W12p + ((size_t)((l - 1) * 512 + 0 * 128 + cta) * 128 + t0) * 32 + lane;
            const uint2* B1 = g_W12p + ((size_t)((l - 1) * 512 + 1 * 128 + cta) * 128 + t0) * 32 + lane;
            const uint2* B2 = g_W12p + ((size_t)((l - 1) * 512 + g2q * 128 + cta) * 128 + t0) * 32 + lane;
            float m0g0[4] = {}, m0g1[4] = {}, m0g2[4] = {};
            float m1g0[4] = {}, m1g1[4] = {}, m1g2[4] = {};
#pragma unroll 1
            for (int i = 0; i < 16; ++i) {
                uint4 a0 = A[i * 32], a1 = A[i * 32 + 128 * 32];
                uint2 b0 = B0[i * 32], b1 = B1[i * 32], b2 = B2[i * 32];
                mma_f16(m0g0, a0, b0.x, b0.y);
                mma_f16(m0g1, a0, b1.x, b1.y);
                mma_f16(m0g2, a0, b2.x, b2.y);
                mma_f16(m1g0, a1, b0.x, b0.y);
                mma_f16(m1g1, a1, b1.x, b1.y);
                mma_f16(m1g2, a1, b2.x, b2.y);
            }
            float* s0 = (l == 1) ? SB1(ksB, mt0, 0) : SB2(ksB, mt0, 0);
            float* s1 = (l == 1) ? SB1(ksB, mt0, 1) : SB2(ksB, mt0, 1);
            float* s2 = (l == 1) ? SB1(ksB, mt0, 2) : SB2(ksB, mt0, 2);
            float* s3 = (l == 1) ? SB1(ksB, mt0 + 1, 0) : SB2(ksB, mt0 + 1, 0);
            float* s4 = (l == 1) ? SB1(ksB, mt0 + 1, 1) : SB2(ksB, mt0 + 1, 1);
            float* s5 = (l == 1) ? SB1(ksB, mt0 + 1, 2) : SB2(ksB, mt0 + 1, 2);
            stD1(s0, rr, cc, m0g0);
            stD1(s1, rr, cc, m0g1);
            stD1(s2, rr, cc, m0g2);
            stD1(s3, rr, cc, m1g0);
            stD1(s4, rr, cc, m1g1);
            stD1(s5, rr, cc, m1g2);
        }

        __syncthreads();

        // ---- unified epilogue: lin(s-3), layer0(s), layer1(s-1), layer2(s-2) ----
        {
            // lin(s-3)
            if (s >= 3) {
                float Do = 0;
#pragma unroll
                for (int sl = 0; sl < 4; ++sl) Do += SA(sl, emm, 3)[er2 * 8 + ejj];
                out[(size_t)eb * NSTEPS * 1024 + (size_t)(s - 3) * 1024 + jcol] = Do + lb;
            }
            // layer0(s)
            if (s < NSTEPS) {
                float Dr = 0, Dz = 0, Dn = 0;
#pragma unroll
                for (int sl = 0; sl < 4; ++sl) {
                    Dr += SA(sl, emm, 0)[er2 * 8 + ejj];
                    Dz += SA(sl, emm, 1)[er2 * 8 + ejj];
                    Dn += SA(sl, emm, 2)[er2 * 8 + ejj];
                }
                float r = sigm(tv0 + Dr + bh0r);
                float z = sigm(tv1 + Dz + bh0z);
                float n = tanhf(tv2 + r * (Dn + bh0n));
                h0s = (1.0f - z) * n + z * h0s;
                storeA(1, ps, eb, jcol, h0s);   // x for layer1 (next superphase)
                storeA(0, ps, eb, jcol, h0s);   // h0 (next superphase)
            }
            // layer1(s-1)
            if (s >= 1 && s < NSTEPS + 1) {
                float Gr = 0, Gz = 0, Gi = 0, Gh = 0;
#pragma unroll
                for (int sl = 0; sl < 8; ++sl) {
                    Gr += SB1(sl, emm, 0)[er2 * 8 + ejj];
                    Gz += SB1(sl, emm, 1)[er2 * 8 + ejj];
                }
#pragma unroll
                for (int sl = 0; sl < 4; ++sl) Gi += SB1(sl, emm, 2)[er2 * 8 + ejj];
#pragma unroll
                for (int sl = 4; sl < 8; ++sl) Gh += SB1(sl, emm, 2)[er2 * 8 + ejj];
                float r = sigm(Gr + bi1r + bh1r);
                float z = sigm(Gz + bi1z + bh1z);
                float n = tanhf(Gi + bi1n + r * (Gh + bh1n));
                h1s = (1.0f - z) * n + z * h1s;
                storeA(2, ps, eb, jcol, h1s);          // x for layer2 (next superphase)
                storeA(1, ps, eb, 1024 + jcol, h1s);   // h1 (next superphase)
            }
            // layer2(s-2)
            if (s >= 2 && s < NSTEPS + 2) {
                float Gr = 0, Gz = 0, Gi = 0, Gh = 0;
#pragma unroll
                for (int sl = 0; sl < 8; ++sl) {
                    Gr += SB2(sl, emm, 0)[er2 * 8 + ejj];
                    Gz += SB2(sl, emm, 1)[er2 * 8 + ejj];
                }
#pragma unroll
                for (int sl = 0; sl < 4; ++sl) Gi += SB2(sl, emm, 2)[er2 * 8 + ejj];
#pragma unroll
                for (int sl = 4; sl < 8; ++sl) Gh += SB2(sl, emm, 2)[er2 * 8 + ejj];
                float r = sigm(Gr + bi2r + bh2r);
                float z = sigm(Gz + bi2z + bh2z);
                float n = tanhf(Gi + bi2n + r * (Gh + bh2n));
                h2s = (1.0f - z) * n + z * h2s;
                storeA(2, ps, eb, 1024 + jcol, h2s);   // h2: layer2 + lin (next superphase)
            }
        }
        gridbar();
    }
    #undef SA
    #undef SB1
    #undef SB2
}

extern "C" void kernel_launch(void* const* d_in, const int* in_sizes, int n_in,
                              void* d_out, int out_size) {
    (void)in_sizes; (void)n_in; (void)out_size;
    const int*   y          = (const int*)  d_in[0];
    // d_in[1] = U (unused by the reference math)
    const float* embed      = (const float*)d_in[2];
    const float* W_ih       = (const float*)d_in[3];
    const float* W_hh       = (const float*)d_in[4];
    const float* b_ih       = (const float*)d_in[5];
    const float* b_hh       = (const float*)d_in[6];
    const float* init_state = (const float*)d_in[7];
    const float* lin_W      = (const float*)d_in[8];
    const float* lin_b      = (const float*)d_in[9];
    float* out = (float*)d_out;

    cudaFuncSetAttribute(decoder_kernel,
                         cudaFuncAttributeMaxDynamicSharedMemorySize, SMEM_TOTAL);
    decoder_kernel<<<NCTA, NTHR, SMEM_TOTAL>>>(y, embed, W_ih, W_hh, b_ih, b_hh,
                                               init_state, lin_W, lin_b, out);
}

// round 15
// speedup vs baseline: 1.7814x; 1.3356x over previous
#include <cuda_runtime.h>
#include <cuda_fp16.h>

#define NV     101          // tokens incl. start symbol (start = 100)
#define UMX    256
#define NSTEPS 257
#define NSUP   (NSTEPS + 3) // skewed superphases
#define G3     3072
#define NCTA   128
#define NTHR   512

typedef unsigned u32;

// ---------------- static device scratch (no runtime allocation) ----------------
// Fragment-packed fp16 weights (single plane).
// g_W0p: job A (K=1024): n-rows 0..3071 = W_hh layer0 (r,z,n), 3072..4095 = lin_W.
//   [ntile(512)][ktile(64)][lane(32)] : uint2 = {W.b0, W.b1}
__device__ __align__(16) uint2 g_W0p[512 * 64 * 32];            // 8 MB
// g_W12p: layers 1,2 (K=2048): per layer n-row q*1024+j:
//   q=0:[Wih_r|Whh_r] q=1:[Wih_z|Whh_z] q=2:[Wih_n|0] q=3:[0|Whh_n]
//   [layer(2)][ntile(512)][ktile(128)][lane(32)]
__device__ __align__(16) uint2 g_W12p[2 * 512 * 128 * 32];      // 32 MB
// Fragment-packed fp16 activations: [l(3)][par(2)][mtile(4)][ktile(128)][lane(32)]
//   l=0: cols 0..1023 = h0; l=1,2: cols 0..1023 = x, 1024..2047 = h_prev
__device__ __align__(16) uint4 g_A[3 * 2 * 4 * 128 * 32];       // 1.5 MB
__device__ float g_T[NV * G3];          // layer0 gi table (incl b_ih0), fp32
__device__ unsigned g_bar;

// ---------------- grid barrier: release-arrive + acquire-poll ----------------
__device__ __forceinline__ void gridbar() {
    __syncthreads();
    if (threadIdx.x == 0) {
        u32 ticket;
        asm volatile("atom.add.release.gpu.global.u32 %0, [%1], 1;"
                     : "=r"(ticket) : "l"(&g_bar) : "memory");
        u32 target = ((ticket + NCTA) / NCTA) * NCTA;
        u32 cur;
        do {
            asm volatile("ld.acquire.gpu.global.u32 %0, [%1];"
                         : "=r"(cur) : "l"(&g_bar) : "memory");
        } while (cur < target);
    }
    __syncthreads();
}

__device__ __forceinline__ float sigm(float t) { return 1.0f / (1.0f + expf(-t)); }

__device__ __forceinline__ u32 hbits(float w) {
    return (u32)__half_as_ushort(__float2half_rn(w));
}
__device__ __forceinline__ uint2 pack2h(float a, float b, float c, float d) {
    uint2 v;
    v.x = hbits(a) | (hbits(b) << 16);   // b0 (k0, k0+1)
    v.y = hbits(c) | (hbits(d) << 16);   // b1 (k0+8, k0+9)
    return v;
}

// A-buffer offset (uint4 units, excluding lane)
__device__ __forceinline__ size_t aoff(int l, int par, int mt, int kt) {
    return (size_t)((((l * 2 + par) * 4 + mt) * 128 + kt)) * 32;
}
// Write activation element (b, c) as fp16 into fragment layout
__device__ __forceinline__ void storeA(int l, int par, int b, int c, float v) {
    int mt = b >> 4, mr = b & 15, kt = c >> 4, kk = c & 15;
    int lane = (mr & 7) * 4 + ((kk & 7) >> 1);
    int slot = (mr >> 3) + ((kk >> 3) << 1);
    __half* p = (__half*)(g_A + aoff(l, par, mt, kt) + lane);
    p[slot * 2 + (kk & 1)] = __float2half_rn(v);
}

// ---------------- mma.m16n8k16 fp16 ----------------
__device__ __forceinline__ void mma_f16(float* d, const uint4& a, u32 b0, u32 b1) {
    asm volatile(
        "mma.sync.aligned.m16n8k16.row.col.f32.f16.f16.f32 "
        "{%0,%1,%2,%3}, {%4,%5,%6,%7}, {%8,%9}, {%0,%1,%2,%3};"
        : "+f"(d[0]), "+f"(d[1]), "+f"(d[2]), "+f"(d[3])
        : "r"(a.x), "r"(a.y), "r"(a.z), "r"(a.w), "r"(b0), "r"(b1));
}
// store a 16x8 tile into smem slab (float[128])
__device__ __forceinline__ void stD1(float* base, int rr, int cc, const float* d) {
    base[rr * 8 + cc]           = d[0];
    base[rr * 8 + cc + 1]       = d[1];
    base[(rr + 8) * 8 + cc]     = d[2];
    base[(rr + 8) * 8 + cc + 1] = d[3];
}

#define SMEM_TOTAL (32768 * 4)   // 128 KB: SA 8K floats + SB1 12K + SB2 12K

// ================================================================================
__global__ void __launch_bounds__(NTHR, 1)
decoder_kernel(const int*   __restrict__ y,
               const float* __restrict__ embed,
               const float* __restrict__ W_ih,
               const float* __restrict__ W_hh,
               const float* __restrict__ b_ih,
               const float* __restrict__ b_hh,
               const float* __restrict__ init_state,
               const float* __restrict__ lin_W,
               const float* __restrict__ lin_b,
               float*       __restrict__ out)
{
    extern __shared__ float sbuf[];
    const int tid  = threadIdx.x;
    const int lane = tid & 31;
    const int wid  = tid >> 5;          // 0..15
    const int mwA  = wid & 3;           // job A: m-tile
    const int ksA  = wid >> 2;          // job A: k-slice 0..3 (16 ktiles each)
    const int mpB  = wid & 1;           // jobs L1/L2: m-half
    const int ksB  = wid >> 1;          // jobs L1/L2: k-slice 0..7 (16 ktiles each)
    const int cta  = blockIdx.x;
    const int gt   = cta * NTHR + tid;
    const int GS   = NCTA * NTHR;
    const int rr   = lane >> 2, cc = (lane & 3) << 1;

    // epilogue element owned by this thread
    const int eb   = tid >> 3;          // batch 0..63
    const int ejj  = tid & 7;
    const int emm  = eb >> 4, er2 = eb & 15;
    const int jcol = cta * 8 + ejj;

    // job A view: [s(4)][mt(4)][q(4)][128]
    #define SA(s_, mt, q) (sbuf + (((s_) * 4 + (mt)) * 4 + (q)) * 128)
    // L1/L2 views: [s(8)][mt(4)][g(3)][128]; g=2 holds i_n for s<4, h_n for s>=4
    #define SB1(s_, mt, g) (sbuf + 8192  + (((s_) * 4 + (mt)) * 3 + (g)) * 128)
    #define SB2(s_, mt, g) (sbuf + 20480 + (((s_) * 4 + (mt)) * 3 + (g)) * 128)

    // ================= PROLOGUE =================
    for (int idx = gt; idx < 512 * 64 * 32; idx += GS) {
        int ln = idx & 31, t = (idx >> 5) & 63, NT = idx >> 11;
        int n  = NT * 8 + (ln >> 2);
        int k0 = t * 16 + ((ln & 3) << 1);
        const float* src = (n < 3072) ? (W_hh + (size_t)n * 1024)
                                      : (lin_W + (size_t)(n - 3072) * 1024);
        g_W0p[idx] = pack2h(src[k0], src[k0 + 1], src[k0 + 8], src[k0 + 9]);
    }
    for (int idx = gt; idx < 2 * 512 * 128 * 32; idx += GS) {
        int ln = idx & 31, t = (idx >> 5) & 127, NT = (idx >> 12) & 511, ll = idx >> 21;
        int n  = NT * 8 + (ln >> 2);
        int qq = n >> 10, jj = n & 1023;
        int k0 = t * 16 + ((ln & 3) << 1);
        int lay = ll + 1;
        float w[4];
#pragma unroll
        for (int i = 0; i < 4; ++i) {
            int k = k0 + ((i >> 1) << 3) + (i & 1);   // k0, k0+1, k0+8, k0+9
            float v = 0.0f;
            if (qq < 2) {
                v = (k < 1024) ? W_ih[((size_t)lay * 3072 + qq * 1024 + jj) * 1024 + k]
                               : W_hh[((size_t)lay * 3072 + qq * 1024 + jj) * 1024 + k - 1024];
            } else if (qq == 2) {
                if (k < 1024) v = W_ih[((size_t)lay * 3072 + 2048 + jj) * 1024 + k];
            } else {
                if (k >= 1024) v = W_hh[((size_t)lay * 3072 + 2048 + jj) * 1024 + k - 1024];
            }
            w[i] = v;
        }
        g_W12p[idx] = pack2h(w[0], w[1], w[2], w[3]);
    }
    // fp32 token table: T[v][row] = embed[v] . W_ih0[row] + b_ih0[row]
    for (int idx = gt; idx < 3072 * 128; idx += GS) {
        int row = idx >> 7, v = idx & 127;
        if (v < NV) {
            const float* e = embed + (size_t)v * 1024;
            const float* w = W_ih + (size_t)row * 1024;
            float a0 = 0, a1 = 0, a2 = 0, a3 = 0;
            for (int k = 0; k < 1024; k += 4) {
                a0 += e[k] * w[k];         a1 += e[k + 1] * w[k + 1];
                a2 += e[k + 2] * w[k + 2]; a3 += e[k + 3] * w[k + 3];
            }
            g_T[v * G3 + row] = (a0 + a1) + (a2 + a3) + b_ih[row];
        }
    }
    // activation init; parity so superphase-0..2 consumers see init values:
    //   h0 read at s=0 (parity 1), h1 read at s=1 (parity 0), h2 read at s=2 (parity 1)
    for (int idx = gt; idx < 3 * 64 * 1024; idx += GS) {
        int l = idx >> 16, r = idx & 65535, b = r >> 10, j = r & 1023;
        float v = init_state[l * 1024 + j];
        int parl = (l == 1) ? 0 : 1;
        storeA(l, parl, b, (l == 0) ? j : (1024 + j), v);
    }

    // ---- per-thread register state + hoisted biases ----
    float h0s = init_state[jcol];
    float h1s = init_state[1024 + jcol];
    float h2s = init_state[2048 + jcol];
    const float bh0r = b_hh[jcol], bh0z = b_hh[1024 + jcol], bh0n = b_hh[2048 + jcol];
    const float bi1r = b_ih[G3 + jcol], bi1z = b_ih[G3 + 1024 + jcol], bi1n = b_ih[G3 + 2048 + jcol];
    const float bh1r = b_hh[G3 + jcol], bh1z = b_hh[G3 + 1024 + jcol], bh1n = b_hh[G3 + 2048 + jcol];
    const float bi2r = b_ih[2 * G3 + jcol], bi2z = b_ih[2 * G3 + 1024 + jcol], bi2n = b_ih[2 * G3 + 2048 + jcol];
    const float bh2r = b_hh[2 * G3 + jcol], bh2z = b_hh[2 * G3 + 1024 + jcol], bh2n = b_hh[2 * G3 + 2048 + jcol];
    const float lb   = lin_b[jcol];

    gridbar();

    // ================= SUPERPHASE LOOP =================
    // superphase s runs: layer0(s), layer1(s-1), layer2(s-2), lin(s-3)
    for (int s = 0; s < NSUP; ++s) {
        const int ps = s & 1, pr = ps ^ 1;

        // ---- prefetch token-table row for layer0(s) (hidden under the GEMMs) ----
        float tv0 = 0.0f, tv1 = 0.0f, tv2 = 0.0f;
        if (s < NSTEPS) {
            int tok = (s == 0) ? (NV - 1) : y[eb * UMX + (s - 1)];
            const float* Tv = g_T + (size_t)tok * G3;
            tv0 = Tv[jcol]; tv1 = Tv[1024 + jcol]; tv2 = Tv[2048 + jcol];
        }

        // ---- job A: layer0 h-GEMM (r,z,n on h0) + lin (on h2), K=1024 ----
        {
            const int t0 = ksA * 16;
            const uint4* A0 = g_A + aoff(0, pr, mwA, t0) + lane;
            const uint4* A2 = g_A + aoff(2, pr, mwA, 64 + t0) + lane;
            const uint2* B0 = g_W0p + ((size_t)(0 * 128 + cta) * 64 + t0) * 32 + lane;
            const uint2* B1 = g_W0p + ((size_t)(1 * 128 + cta) * 64 + t0) * 32 + lane;
            const uint2* B2 = g_W0p + ((size_t)(2 * 128 + cta) * 64 + t0) * 32 + lane;
            const uint2* B3 = g_W0p + ((size_t)(3 * 128 + cta) * 64 + t0) * 32 + lane;
            float d0[4] = {}, d1[4] = {}, d2[4] = {}, d3[4] = {};
#pragma unroll 1
            for (int i = 0; i < 16; i += 2) {
                // batch ALL loads for 2 ktiles first (12 independent LDGs)
                uint4 a_0 = A0[i * 32],       c_0 = A2[i * 32];
                uint4 a_1 = A0[(i + 1) * 32], c_1 = A2[(i + 1) * 32];
                uint2 b0_0 = B0[i * 32],       b1_0 = B1[i * 32];
                uint2 b2_0 = B2[i * 32],       b3_0 = B3[i * 32];
                uint2 b0_1 = B0[(i + 1) * 32], b1_1 = B1[(i + 1) * 32];
                uint2 b2_1 = B2[(i + 1) * 32], b3_1 = B3[(i + 1) * 32];
                mma_f16(d0, a_0, b0_0.x, b0_0.y);
                mma_f16(d1, a_0, b1_0.x, b1_0.y);
                mma_f16(d2, a_0, b2_0.x, b2_0.y);
                mma_f16(d3, c_0, b3_0.x, b3_0.y);
                mma_f16(d0, a_1, b0_1.x, b0_1.y);
                mma_f16(d1, a_1, b1_1.x, b1_1.y);
                mma_f16(d2, a_1, b2_1.x, b2_1.y);
                mma_f16(d3, c_1, b3_1.x, b3_1.y);
            }
            stD1(SA(ksA, mwA, 0), rr, cc, d0);
            stD1(SA(ksA, mwA, 1), rr, cc, d1);
            stD1(SA(ksA, mwA, 2), rr, cc, d2);
            stD1(SA(ksA, mwA, 3), rr, cc, d3);
        }

        // ---- jobs L1 (layer1(s-1)) and L2 (layer2(s-2)), K=2048 ----
#pragma unroll 1
        for (int l = 1; l <= 2; ++l) {
            const int t0  = ksB * 16;
            const int g2q = 2 + (ksB >> 2);        // i_n for ks<4, h_n for ks>=4
            const int mt0 = mpB * 2;
            const uint4* A  = g_A + aoff(l, pr, mt0, t0) + lane;
            const uint2* B0 = g_W12p + ((size_t)((l - 1) * 512 + 0 * 128 + cta) * 128 + t0) * 32 + lane;
            const uint2* B1 = g_W12p + ((size_t)((l - 1) * 512 + 1 * 128 + cta) * 128 + t0) * 32 + lane;
            const uint2* B2 = g_W12p + ((size_t)((l - 1) * 512 + g2q * 128 + cta) * 128 + t0) * 32 + lane;
            float m0g0[4] = {}, m0g1[4] = {}, m0g2[4] = {};
            float m1g0[4] = {}, m1g1[4] = {}, m1g2[4] = {};
#pragma unroll 1
            for (int i = 0; i < 16; i += 2) {
                // batch ALL loads for 2 ktiles first (10 independent LDGs)
                uint4 a0_0 = A[i * 32],       a1_0 = A[i * 32 + 128 * 32];
                uint4 a0_1 = A[(i + 1) * 32], a1_1 = A[(i + 1) * 32 + 128 * 32];
                uint2 b0_0 = B0[i * 32],       b1_0 = B1[i * 32],       b2_0 = B2[i * 32];
                uint2 b0_1 = B0[(i + 1) * 32], b1_1 = B1[(i + 1) * 32], b2_1 = B2[(i + 1) * 32];
                mma_f16(m0g0, a0_0, b0_0.x, b0_0.y);
                mma_f16(m0g1, a0_0, b1_0.x, b1_0.y);
                mma_f16(m0g2, a0_0, b2_0.x, b2_0.y);
                mma_f16(m1g0, a1_0, b0_0.x, b0_0.y);
                mma_f16(m1g1, a1_0, b1_0.x, b1_0.y);
                mma_f16(m1g2, a1_0, b2_0.x, b2_0.y);
                mma_f16(m0g0, a0_1, b0_1.x, b0_1.y);
                mma_f16(m0g1, a0_1, b1_1.x, b1_1.y);
                mma_f16(m0g2, a0_1, b2_1.x, b2_1.y);
                mma_f16(m1g0, a1_1, b0_1.x, b0_1.y);
                mma_f16(m1g1, a1_1, b1_1.x, b1_1.y);
                mma_f16(m1g2, a1_1, b2_1.x, b2_1.y);
            }
            float* s0 = (l == 1) ? SB1(ksB, mt0, 0) : SB2(ksB, mt0, 0);
            float* s1 = (l == 1) ? SB1(ksB, mt0, 1) : SB2(ksB, mt0, 1);
            float* s2 = (l == 1) ? SB1(ksB, mt0, 2) : SB2(ksB, mt0, 2);
            float* s3 = (l == 1) ? SB1(ksB, mt0 + 1, 0) : SB2(ksB, mt0 + 1, 0);
            float* s4 = (l == 1) ? SB1(ksB, mt0 + 1, 1) : SB2(ksB, mt0 + 1, 1);
            float* s5 = (l == 1) ? SB1(ksB, mt0 + 1, 2) : SB2(ksB, mt0 + 1, 2);
            stD1(s0, rr, cc, m0g0);
            stD1(s1, rr, cc, m0g1);
            stD1(s2, rr, cc, m0g2);
            stD1(s3, rr, cc, m1g0);
            stD1(s4, rr, cc, m1g1);
            stD1(s5, rr, cc, m1g2);
        }

        __syncthreads();

        // ---- unified epilogue: lin(s-3), layer0(s), layer1(s-1), layer2(s-2) ----
        {
            // lin(s-3)
            if (s >= 3) {
                float Do = 0;
#pragma unroll
                for (int sl = 0; sl < 4; ++sl) Do += SA(sl, emm, 3)[er2 * 8 + ejj];
                out[(size_t)eb * NSTEPS * 1024 + (size_t)(s - 3) * 1024 + jcol] = Do + lb;
            }
            // layer0(s)
            if (s < NSTEPS) {
                float Dr = 0, Dz = 0, Dn = 0;
#pragma unroll
                for (int sl = 0; sl < 4; ++sl) {
                    Dr += SA(sl, emm, 0)[er2 * 8 + ejj];
                    Dz += SA(sl, emm, 1)[er2 * 8 + ejj];
                    Dn += SA(sl, emm, 2)[er2 * 8 + ejj];
                }
                float r = sigm(tv0 + Dr + bh0r);
                float z = sigm(tv1 + Dz + bh0z);
                float n = tanhf(tv2 + r * (Dn + bh0n));
                h0s = (1.0f - z) * n + z * h0s;
                storeA(1, ps, eb, jcol, h0s);   // x for layer1 (next superphase)
                storeA(0, ps, eb, jcol, h0s);   // h0 (next superphase)
            }
            // layer1(s-1)
            if (s >= 1 && s < NSTEPS + 1) {
                float Gr = 0, Gz = 0, Gi = 0, Gh = 0;
#pragma unroll
                for (int sl = 0; sl < 8; ++sl) {
                    Gr += SB1(sl, emm, 0)[er2 * 8 + ejj];
                    Gz += SB1(sl, emm, 1)[er2 * 8 + ejj];
                }
#pragma unroll
                for (int sl = 0; sl < 4; ++sl) Gi += SB1(sl, emm, 2)[er2 * 8 + ejj];
#pragma unroll
                for (int sl = 4; sl < 8; ++sl) Gh += SB1(sl, emm, 2)[er2 * 8 + ejj];
                float r = sigm(Gr + bi1r + bh1r);
                float z = sigm(Gz + bi1z + bh1z);
                float n = tanhf(Gi + bi1n + r * (Gh + bh1n));
                h1s = (1.0f - z) * n + z * h1s;
                storeA(2, ps, eb, jcol, h1s);          // x for layer2 (next superphase)
                storeA(1, ps, eb, 1024 + jcol, h1s);   // h1 (next superphase)
            }
            // layer2(s-2)
            if (s >= 2 && s < NSTEPS + 2) {
                float Gr = 0, Gz = 0, Gi = 0, Gh = 0;
#pragma unroll
                for (int sl = 0; sl < 8; ++sl) {
                    Gr += SB2(sl, emm, 0)[er2 * 8 + ejj];
                    Gz += SB2(sl, emm, 1)[er2 * 8 + ejj];
                }
#pragma unroll
                for (int sl = 0; sl < 4; ++sl) Gi += SB2(sl, emm, 2)[er2 * 8 + ejj];
#pragma unroll
                for (int sl = 4; sl < 8; ++sl) Gh += SB2(sl, emm, 2)[er2 * 8 + ejj];
                float r = sigm(Gr + bi2r + bh2r);
                float z = sigm(Gz + bi2z + bh2z);
                float n = tanhf(Gi + bi2n + r * (Gh + bh2n));
                h2s = (1.0f - z) * n + z * h2s;
                storeA(2, ps, eb, 1024 + jcol, h2s);   // h2: layer2 + lin (next superphase)
            }
        }
        gridbar();
    }
    #undef SA
    #undef SB1
    #undef SB2
}

extern "C" void kernel_launch(void* const* d_in, const int* in_sizes, int n_in,
                              void* d_out, int out_size) {
    (void)in_sizes; (void)n_in; (void)out_size;
    const int*   y          = (const int*)  d_in[0];
    // d_in[1] = U (unused by the reference math)
    const float* embed      = (const float*)d_in[2];
    const float* W_ih       = (const float*)d_in[3];
    const float* W_hh       = (const float*)d_in[4];
    const float* b_ih       = (const float*)d_in[5];
    const float* b_hh       = (const float*)d_in[6];
    const float* init_state = (const float*)d_in[7];
    const float* lin_W      = (const float*)d_in[8];
    const float* lin_b      = (const float*)d_in[9];
    float* out = (float*)d_out;

    cudaFuncSetAttribute(decoder_kernel,
                         cudaFuncAttributeMaxDynamicSharedMemorySize, SMEM_TOTAL);
    decoder_kernel<<<NCTA, NTHR, SMEM_TOTAL>>>(y, embed, W_ih, W_hh, b_ih, b_hh,
                                               init_state, lin_W, lin_b, out);
}

// round 16
// speedup vs baseline: 1.8134x; 1.0180x over previous
#include <cuda_runtime.h>
#include <cuda_fp16.h>

#define NV     101          // tokens incl. start symbol (start = 100)
#define UMX    256
#define NSTEPS 257
#define NSUP   (NSTEPS + 3) // skewed superphases
#define G3     3072
#define NCTA   128
#define NTHR   512

typedef unsigned u32;

// ---------------- static device scratch (no runtime allocation) ----------------
// Fragment-packed fp16 weights, gate-pair fused.
// g_W0q: job A (K=1024): [cta(128)][ktile(64)][half(2)][lane(32)] uint4
//   half0 = gates {r,z} of W_hh layer0; half1 = {n gate, lin_W} — each uint4 holds two
//   gates' (b0,b1) fragments for this (ktile, lane).
__device__ __align__(16) uint4 g_W0q[128 * 64 * 2 * 32];        // 8 MB
// g_W12q4: layers 1,2: gates {r,z} fused: [layer(2)][cta(128)][ktile(128)][lane(32)] uint4
__device__ __align__(16) uint4 g_W12q4[2 * 128 * 128 * 32];     // 16 MB
// g_W12q2: layers 1,2: n-gate merged stream: ktile<64 = Wih_n (k=ktile*16),
//   ktile>=64 = Whh_n (k=(ktile-64)*16): [layer][cta][ktile(128)][lane] uint2
__device__ __align__(16) uint2 g_W12q2[2 * 128 * 128 * 32];     // 8 MB
// Fragment-packed fp16 activations: [l(3)][par(2)][mtile(4)][ktile(128)][lane(32)]
//   l=0: cols 0..1023 = h0; l=1,2: cols 0..1023 = x, 1024..2047 = h_prev
__device__ __align__(16) uint4 g_A[3 * 2 * 4 * 128 * 32];       // 1.5 MB
__device__ float g_T[NV * G3];          // layer0 gi table (incl b_ih0), fp32
__device__ unsigned g_bar;

// ---------------- grid barrier: release-arrive + acquire-poll ----------------
__device__ __forceinline__ void gridbar() {
    __syncthreads();
    if (threadIdx.x == 0) {
        u32 ticket;
        asm volatile("atom.add.release.gpu.global.u32 %0, [%1], 1;"
                     : "=r"(ticket) : "l"(&g_bar) : "memory");
        u32 target = ((ticket + NCTA) / NCTA) * NCTA;
        u32 cur;
        do {
            asm volatile("ld.acquire.gpu.global.u32 %0, [%1];"
                         : "=r"(cur) : "l"(&g_bar) : "memory");
        } while (cur < target);
    }
    __syncthreads();
}

__device__ __forceinline__ float sigm(float t) { return 1.0f / (1.0f + expf(-t)); }

__device__ __forceinline__ u32 hbits(float w) {
    return (u32)__half_as_ushort(__float2half_rn(w));
}
__device__ __forceinline__ uint2 pack2h(float a, float b, float c, float d) {
    uint2 v;
    v.x = hbits(a) | (hbits(b) << 16);   // b0 (k0, k0+1)
    v.y = hbits(c) | (hbits(d) << 16);   // b1 (k0+8, k0+9)
    return v;
}

// ---------------- cache-policy loads ----------------
// A: read-once streaming — do not allocate in L1 (keeps carveout free for B,
//    and avoids stale-line hazards on the double-buffered activation regions).
__device__ __forceinline__ uint4 ldgA(const uint4* p) {
    uint4 v;
    asm volatile("ld.global.L1::no_allocate.v4.u32 {%0,%1,%2,%3}, [%4];"
                 : "=r"(v.x), "=r"(v.y), "=r"(v.z), "=r"(v.w) : "l"(p));
    return v;
}
// B: constant weights, identical working set every superphase — pin in L1.
__device__ __forceinline__ uint4 ldgB4(const uint4* p) {
    uint4 v;
    asm volatile("ld.global.L1::evict_last.v4.u32 {%0,%1,%2,%3}, [%4];"
                 : "=r"(v.x), "=r"(v.y), "=r"(v.z), "=r"(v.w) : "l"(p));
    return v;
}
__device__ __forceinline__ uint2 ldgB2(const uint2* p) {
    uint2 v;
    asm volatile("ld.global.L1::evict_last.v2.u32 {%0,%1}, [%2];"
                 : "=r"(v.x), "=r"(v.y) : "l"(p));
    return v;
}

// A-buffer offset (uint4 units, excluding lane)
__device__ __forceinline__ size_t aoff(int l, int par, int mt, int kt) {
    return (size_t)((((l * 2 + par) * 4 + mt) * 128 + kt)) * 32;
}
// Write activation element (b, c) as fp16 into fragment layout
__device__ __forceinline__ void storeA(int l, int par, int b, int c, float v) {
    int mt = b >> 4, mr = b & 15, kt = c >> 4, kk = c & 15;
    int lane = (mr & 7) * 4 + ((kk & 7) >> 1);
    int slot = (mr >> 3) + ((kk >> 3) << 1);
    __half* p = (__half*)(g_A + aoff(l, par, mt, kt) + lane);
    p[slot * 2 + (kk & 1)] = __float2half_rn(v);
}

// ---------------- mma.m16n8k16 fp16 ----------------
__device__ __forceinline__ void mma_f16(float* d, const uint4& a, u32 b0, u32 b1) {
    asm volatile(
        "mma.sync.aligned.m16n8k16.row.col.f32.f16.f16.f32 "
        "{%0,%1,%2,%3}, {%4,%5,%6,%7}, {%8,%9}, {%0,%1,%2,%3};"
        : "+f"(d[0]), "+f"(d[1]), "+f"(d[2]), "+f"(d[3])
        : "r"(a.x), "r"(a.y), "r"(a.z), "r"(a.w), "r"(b0), "r"(b1));
}
// store a 16x8 tile into smem slab (float[128])
__device__ __forceinline__ void stD1(float* base, int rr, int cc, const float* d) {
    base[rr * 8 + cc]           = d[0];
    base[rr * 8 + cc + 1]       = d[1];
    base[(rr + 8) * 8 + cc]     = d[2];
    base[(rr + 8) * 8 + cc + 1] = d[3];
}

#define SMEM_TOTAL (32768 * 4)   // 128 KB: SA 8K floats + SB1 12K + SB2 12K

// ================================================================================
__global__ void __launch_bounds__(NTHR, 1)
decoder_kernel(const int*   __restrict__ y,
               const float* __restrict__ embed,
               const float* __restrict__ W_ih,
               const float* __restrict__ W_hh,
               const float* __restrict__ b_ih,
               const float* __restrict__ b_hh,
               const float* __restrict__ init_state,
               const float* __restrict__ lin_W,
               const float* __restrict__ lin_b,
               float*       __restrict__ out)
{
    extern __shared__ float sbuf[];
    const int tid  = threadIdx.x;
    const int lane = tid & 31;
    const int wid  = tid >> 5;          // 0..15
    const int mwA  = wid & 3;           // job A: m-tile
    const int ksA  = wid >> 2;          // job A: k-slice 0..3 (16 ktiles each)
    const int mpB  = wid & 1;           // jobs L1/L2: m-half
    const int ksB  = wid >> 1;          // jobs L1/L2: k-slice 0..7 (16 ktiles each)
    const int cta  = blockIdx.x;
    const int gt   = cta * NTHR + tid;
    const int GS   = NCTA * NTHR;
    const int rr   = lane >> 2, cc = (lane & 3) << 1;

    // epilogue element owned by this thread
    const int eb   = tid >> 3;          // batch 0..63
    const int ejj  = tid & 7;
    const int emm  = eb >> 4, er2 = eb & 15;
    const int jcol = cta * 8 + ejj;

    // job A view: [s(4)][mt(4)][q(4)][128]
    #define SA(s_, mt, q) (sbuf + (((s_) * 4 + (mt)) * 4 + (q)) * 128)
    // L1/L2 views: [s(8)][mt(4)][g(3)][128]; g=2 holds i_n for s<4, h_n for s>=4
    #define SB1(s_, mt, g) (sbuf + 8192  + (((s_) * 4 + (mt)) * 3 + (g)) * 128)
    #define SB2(s_, mt, g) (sbuf + 20480 + (((s_) * 4 + (mt)) * 3 + (g)) * 128)

    // ================= PROLOGUE =================
    // job A weights, gate-pair fused: half0={r,z}, half1={n, lin}
    for (int idx = gt; idx < 128 * 64 * 2 * 32; idx += GS) {
        int ln = idx & 31, hf = (idx >> 5) & 1, t = (idx >> 6) & 63, ci = idx >> 12;
        int k0 = t * 16 + ((ln & 3) << 1);
        uint2 fr[2];
#pragma unroll
        for (int g = 0; g < 2; ++g) {
            int q = hf * 2 + g;
            int n = q * 1024 + ci * 8 + (ln >> 2);
            const float* src = (n < 3072) ? (W_hh + (size_t)n * 1024)
                                          : (lin_W + (size_t)(n - 3072) * 1024);
            fr[g] = pack2h(src[k0], src[k0 + 1], src[k0 + 8], src[k0 + 9]);
        }
        g_W0q[idx] = make_uint4(fr[0].x, fr[0].y, fr[1].x, fr[1].y);
    }
    // layers 1/2 gates {r,z} fused (K=2048: k<1024 from W_ih, else W_hh)
    for (int idx = gt; idx < 2 * 128 * 128 * 32; idx += GS) {
        int ln = idx & 31, t = (idx >> 5) & 127, ci = (idx >> 12) & 127, ll = idx >> 19;
        int lay = ll + 1;
        int k0 = t * 16 + ((ln & 3) << 1);
        int jj = ci * 8 + (ln >> 2);
        uint2 fr[2];
#pragma unroll
        for (int q = 0; q < 2; ++q) {
            size_t row = (size_t)(lay * 3072 + q * 1024 + jj);
            float w[4];
#pragma unroll
            for (int i = 0; i < 4; ++i) {
                int k = k0 + ((i >> 1) << 3) + (i & 1);   // k0, k0+1, k0+8, k0+9
                w[i] = (k < 1024) ? W_ih[row * 1024 + k] : W_hh[row * 1024 + k - 1024];
            }
            fr[q] = pack2h(w[0], w[1], w[2], w[3]);
        }
        g_W12q4[idx] = make_uint4(fr[0].x, fr[0].y, fr[1].x, fr[1].y);
    }
    // layers 1/2 n-gate merged stream: ktile<64 = Wih_n, ktile>=64 = Whh_n
    for (int idx = gt; idx < 2 * 128 * 128 * 32; idx += GS) {
        int ln = idx & 31, t = (idx >> 5) & 127, ci = (idx >> 12) & 127, ll = idx >> 19;
        int lay = ll + 1;
        int jj = ci * 8 + (ln >> 2);
        size_t row = (size_t)(lay * 3072 + 2048 + jj);
        const float* src;
        int kb;
        if (t < 64) { src = W_ih + row * 1024; kb = t * 16 + ((ln & 3) << 1); }
        else        { src = W_hh + row * 1024; kb = (t - 64) * 16 + ((ln & 3) << 1); }
        g_W12q2[idx] = pack2h(src[kb], src[kb + 1], src[kb + 8], src[kb + 9]);
    }
    // fp32 token table: T[v][row] = embed[v] . W_ih0[row] + b_ih0[row]
    for (int idx = gt; idx < 3072 * 128; idx += GS) {
        int row = idx >> 7, v = idx & 127;
        if (v < NV) {
            const float* e = embed + (size_t)v * 1024;
            const float* w = W_ih + (size_t)row * 1024;
            float a0 = 0, a1 = 0, a2 = 0, a3 = 0;
            for (int k = 0; k < 1024; k += 4) {
                a0 += e[k] * w[k];         a1 += e[k + 1] * w[k + 1];
                a2 += e[k + 2] * w[k + 2]; a3 += e[k + 3] * w[k + 3];
            }
            g_T[v * G3 + row] = (a0 + a1) + (a2 + a3) + b_ih[row];
        }
    }
    // activation init; parity so superphase-0..2 consumers see init values:
    //   h0 read at s=0 (parity 1), h1 read at s=1 (parity 0), h2 read at s=2 (parity 1)
    for (int idx = gt; idx < 3 * 64 * 1024; idx += GS) {
        int l = idx >> 16, r = idx & 65535, b = r >> 10, j = r & 1023;
        float v = init_state[l * 1024 + j];
        int parl = (l == 1) ? 0 : 1;
        storeA(l, parl, b, (l == 0) ? j : (1024 + j), v);
    }

    // ---- per-thread register state + hoisted biases ----
    float h0s = init_state[jcol];
    float h1s = init_state[1024 + jcol];
    float h2s = init_state[2048 + jcol];
    const float bh0r = b_hh[jcol], bh0z = b_hh[1024 + jcol], bh0n = b_hh[2048 + jcol];
    const float bi1r = b_ih[G3 + jcol], bi1z = b_ih[G3 + 1024 + jcol], bi1n = b_ih[G3 + 2048 + jcol];
    const float bh1r = b_hh[G3 + jcol], bh1z = b_hh[G3 + 1024 + jcol], bh1n = b_hh[G3 + 2048 + jcol];
    const float bi2r = b_ih[2 * G3 + jcol], bi2z = b_ih[2 * G3 + 1024 + jcol], bi2n = b_ih[2 * G3 + 2048 + jcol];
    const float bh2r = b_hh[2 * G3 + jcol], bh2z = b_hh[2 * G3 + 1024 + jcol], bh2n = b_hh[2 * G3 + 2048 + jcol];
    const float lb   = lin_b[jcol];

    gridbar();

    // ================= SUPERPHASE LOOP =================
    // superphase s runs: layer0(s), layer1(s-1), layer2(s-2), lin(s-3)
    for (int s = 0; s < NSUP; ++s) {
        const int ps = s & 1, pr = ps ^ 1;

        // ---- prefetch token-table row for layer0(s) (hidden under the GEMMs) ----
        float tv0 = 0.0f, tv1 = 0.0f, tv2 = 0.0f;
        if (s < NSTEPS) {
            int tok = (s == 0) ? (NV - 1) : y[eb * UMX + (s - 1)];
            const float* Tv = g_T + (size_t)tok * G3;
            tv0 = Tv[jcol]; tv1 = Tv[1024 + jcol]; tv2 = Tv[2048 + jcol];
        }

        // ---- job A: layer0 h-GEMM (r,z,n on h0) + lin (on h2), K=1024 ----
        {
            const int t0 = ksA * 16;
            const uint4* A0 = g_A + aoff(0, pr, mwA, t0) + lane;
            const uint4* A2 = g_A + aoff(2, pr, mwA, 64 + t0) + lane;
            const uint4* BA = g_W0q + ((size_t)(cta * 64 + t0) * 2) * 32 + lane;
            float d0[4] = {}, d1[4] = {}, d2[4] = {}, d3[4] = {};
#pragma unroll 1
            for (int i = 0; i < 16; i += 2) {
                // batch ALL loads for 2 ktiles (8 independent LDGs)
                uint4 a_0 = ldgA(A0 + i * 32),       c_0 = ldgA(A2 + i * 32);
                uint4 a_1 = ldgA(A0 + (i + 1) * 32), c_1 = ldgA(A2 + (i + 1) * 32);
                uint4 p_0 = ldgB4(BA + i * 64),       r_0 = ldgB4(BA + i * 64 + 32);
                uint4 p_1 = ldgB4(BA + (i + 1) * 64), r_1 = ldgB4(BA + (i + 1) * 64 + 32);
                mma_f16(d0, a_0, p_0.x, p_0.y);
                mma_f16(d1, a_0, p_0.z, p_0.w);
                mma_f16(d2, a_0, r_0.x, r_0.y);
                mma_f16(d3, c_0, r_0.z, r_0.w);
                mma_f16(d0, a_1, p_1.x, p_1.y);
                mma_f16(d1, a_1, p_1.z, p_1.w);
                mma_f16(d2, a_1, r_1.x, r_1.y);
                mma_f16(d3, c_1, r_1.z, r_1.w);
            }
            stD1(SA(ksA, mwA, 0), rr, cc, d0);
            stD1(SA(ksA, mwA, 1), rr, cc, d1);
            stD1(SA(ksA, mwA, 2), rr, cc, d2);
            stD1(SA(ksA, mwA, 3), rr, cc, d3);
        }

        // ---- jobs L1 (layer1(s-1)) and L2 (layer2(s-2)), K=2048 ----
#pragma unroll 1
        for (int l = 1; l <= 2; ++l) {
            const int t0  = ksB * 16;
            const int mt0 = mpB * 2;
            const uint4* A   = g_A + aoff(l, pr, mt0, t0) + lane;
            const uint4* B01 = g_W12q4 + ((size_t)((l - 1) * 128 + cta) * 128 + t0) * 32 + lane;
            const uint2* B23 = g_W12q2 + ((size_t)((l - 1) * 128 + cta) * 128 + t0) * 32 + lane;
            float m0g0[4] = {}, m0g1[4] = {}, m0g2[4] = {};
            float m1g0[4] = {}, m1g1[4] = {}, m1g2[4] = {};
#pragma unroll 1
            for (int i = 0; i < 16; i += 2) {
                // batch ALL loads for 2 ktiles (8 independent LDGs)
                uint4 a0_0 = ldgA(A + i * 32),       a1_0 = ldgA(A + i * 32 + 128 * 32);
                uint4 a0_1 = ldgA(A + (i + 1) * 32), a1_1 = ldgA(A + (i + 1) * 32 + 128 * 32);
                uint4 w_0 = ldgB4(B01 + i * 32), w_1 = ldgB4(B01 + (i + 1) * 32);
                uint2 v_0 = ldgB2(B23 + i * 32), v_1 = ldgB2(B23 + (i + 1) * 32);
                mma_f16(m0g0, a0_0, w_0.x, w_0.y);
                mma_f16(m0g1, a0_0, w_0.z, w_0.w);
                mma_f16(m0g2, a0_0, v_0.x, v_0.y);
                mma_f16(m1g0, a1_0, w_0.x, w_0.y);
                mma_f16(m1g1, a1_0, w_0.z, w_0.w);
                mma_f16(m1g2, a1_0, v_0.x, v_0.y);
                mma_f16(m0g0, a0_1, w_1.x, w_1.y);
                mma_f16(m0g1, a0_1, w_1.z, w_1.w);
                mma_f16(m0g2, a0_1, v_1.x, v_1.y);
                mma_f16(m1g0, a1_1, w_1.x, w_1.y);
                mma_f16(m1g1, a1_1, w_1.z, w_1.w);
                mma_f16(m1g2, a1_1, v_1.x, v_1.y);
            }
            float* s0 = (l == 1) ? SB1(ksB, mt0, 0) : SB2(ksB, mt0, 0);
            float* s1 = (l == 1) ? SB1(ksB, mt0, 1) : SB2(ksB, mt0, 1);
            float* s2 = (l == 1) ? SB1(ksB, mt0, 2) : SB2(ksB, mt0, 2);
            float* s3 = (l == 1) ? SB1(ksB, mt0 + 1, 0) : SB2(ksB, mt0 + 1, 0);
            float* s4 = (l == 1) ? SB1(ksB, mt0 + 1, 1) : SB2(ksB, mt0 + 1, 1);
            float* s5 = (l == 1) ? SB1(ksB, mt0 + 1, 2) : SB2(ksB, mt0 + 1, 2);
            stD1(s0, rr, cc, m0g0);
            stD1(s1, rr, cc, m0g1);
            stD1(s2, rr, cc, m0g2);
            stD1(s3, rr, cc, m1g0);
            stD1(s4, rr, cc, m1g1);
            stD1(s5, rr, cc, m1g2);
        }

        __syncthreads();

        // ---- unified epilogue: lin(s-3), layer0(s), layer1(s-1), layer2(s-2) ----
        {
            // lin(s-3)
            if (s >= 3) {
                float Do = 0;
#pragma unroll
                for (int sl = 0; sl < 4; ++sl) Do += SA(sl, emm, 3)[er2 * 8 + ejj];
                out[(size_t)eb * NSTEPS * 1024 + (size_t)(s - 3) * 1024 + jcol] = Do + lb;
            }
            // layer0(s)
            if (s < NSTEPS) {
                float Dr = 0, Dz = 0, Dn = 0;
#pragma unroll
                for (int sl = 0; sl < 4; ++sl) {
                    Dr += SA(sl, emm, 0)[er2 * 8 + ejj];
                    Dz += SA(sl, emm, 1)[er2 * 8 + ejj];
                    Dn += SA(sl, emm, 2)[er2 * 8 + ejj];
                }
                float r = sigm(tv0 + Dr + bh0r);
                float z = sigm(tv1 + Dz + bh0z);
                float n = tanhf(tv2 + r * (Dn + bh0n));
                h0s = (1.0f - z) * n + z * h0s;
                storeA(1, ps, eb, jcol, h0s);   // x for layer1 (next superphase)
                storeA(0, ps, eb, jcol, h0s);   // h0 (next superphase)
            }
            // layer1(s-1)
            if (s >= 1 && s < NSTEPS + 1) {
                float Gr = 0, Gz = 0, Gi = 0, Gh = 0;
#pragma unroll
                for (int sl = 0; sl < 8; ++sl) {
                    Gr += SB1(sl, emm, 0)[er2 * 8 + ejj];
                    Gz += SB1(sl, emm, 1)[er2 * 8 + ejj];
                }
#pragma unroll
                for (int sl = 0; sl < 4; ++sl) Gi += SB1(sl, emm, 2)[er2 * 8 + ejj];
#pragma unroll
                for (int sl = 4; sl < 8; ++sl) Gh += SB1(sl, emm, 2)[er2 * 8 + ejj];
                float r = sigm(Gr + bi1r + bh1r);
                float z = sigm(Gz + bi1z + bh1z);
                float n = tanhf(Gi + bi1n + r * (Gh + bh1n));
                h1s = (1.0f - z) * n + z * h1s;
                storeA(2, ps, eb, jcol, h1s);          // x for layer2 (next superphase)
                storeA(1, ps, eb, 1024 + jcol, h1s);   // h1 (next superphase)
            }
            // layer2(s-2)
            if (s >= 2 && s < NSTEPS + 2) {
                float Gr = 0, Gz = 0, Gi = 0, Gh = 0;
#pragma unroll
                for (int sl = 0; sl < 8; ++sl) {
                    Gr += SB2(sl, emm, 0)[er2 * 8 + ejj];
                    Gz += SB2(sl, emm, 1)[er2 * 8 + ejj];
                }
#pragma unroll
                for (int sl = 0; sl < 4; ++sl) Gi += SB2(sl, emm, 2)[er2 * 8 + ejj];
#pragma unroll
                for (int sl = 4; sl < 8; ++sl) Gh += SB2(sl, emm, 2)[er2 * 8 + ejj];
                float r = sigm(Gr + bi2r + bh2r);
                float z = sigm(Gz + bi2z + bh2z);
                float n = tanhf(Gi + bi2n + r * (Gh + bh2n));
                h2s = (1.0f - z) * n + z * h2s;
                storeA(2, ps, eb, 1024 + jcol, h2s);   // h2: layer2 + lin (next superphase)
            }
        }
        gridbar();
    }
    #undef SA
    #undef SB1
    #undef SB2
}

extern "C" void kernel_launch(void* const* d_in, const int* in_sizes, int n_in,
                              void* d_out, int out_size) {
    (void)in_sizes; (void)n_in; (void)out_size;
    const int*   y          = (const int*)  d_in[0];
    // d_in[1] = U (unused by the reference math)
    const float* embed      = (const float*)d_in[2];
    const float* W_ih       = (const float*)d_in[3];
    const float* W_hh       = (const float*)d_in[4];
    const float* b_ih       = (const float*)d_in[5];
    const float* b_hh       = (const float*)d_in[6];
    const float* init_state = (const float*)d_in[7];
    const float* lin_W      = (const float*)d_in[8];
    const float* lin_b      = (const float*)d_in[9];
    float* out = (float*)d_out;

    cudaFuncSetAttribute(decoder_kernel,
                         cudaFuncAttributeMaxDynamicSharedMemorySize, SMEM_TOTAL);
    decoder_kernel<<<NCTA, NTHR, SMEM_TOTAL>>>(y, embed, W_ih, W_hh, b_ih, b_hh,
                                               init_state, lin_W, lin_b, out);
}

// round 17
// speedup vs baseline: 1.8548x; 1.0228x over previous
#include <cuda_runtime.h>
#include <cuda_fp16.h>

#define NV     101          // tokens incl. start symbol (start = 100)
#define UMX    256
#define NSTEPS 257
#define NSUP   (NSTEPS + 3) // skewed superphases
#define G3     3072
#define NCTA   128
#define NTHR   512

typedef unsigned u32;

// ---------------- static device scratch (no runtime allocation) ----------------
// Fragment-packed fp16 weights, gate-pair fused.
// g_W0q: job A (K=1024): [cta(128)][ktile(64)][half(2)][lane(32)] uint4
//   half0 = gates {r,z} of W_hh layer0; half1 = {n gate, lin_W}
__device__ __align__(16) uint4 g_W0q[128 * 64 * 2 * 32];        // 8 MB
// g_W12q4: layers 1,2: gates {r,z} fused: [layer(2)][cta(128)][ktile(128)][lane(32)] uint4
__device__ __align__(16) uint4 g_W12q4[2 * 128 * 128 * 32];     // 16 MB
// g_W12q2: layers 1,2: n-gate merged stream: ktile<64 = Wih_n, ktile>=64 = Whh_n
__device__ __align__(16) uint2 g_W12q2[2 * 128 * 128 * 32];     // 8 MB
// Fragment-packed fp16 activations: [l(3)][par(2)][mtile(4)][ktile(128)][lane(32)]
//   l=0: cols 0..1023 = h0; l=1,2: cols 0..1023 = x, 1024..2047 = h_prev
__device__ __align__(16) uint4 g_A[3 * 2 * 4 * 128 * 32];       // 1.5 MB
__device__ float g_T[NV * G3];          // layer0 gi table (incl b_ih0), fp32
__device__ unsigned g_bar;

// ---------------- grid barrier: release-arrive + acquire-poll ----------------
__device__ __forceinline__ void gridbar() {
    __syncthreads();
    if (threadIdx.x == 0) {
        u32 ticket;
        asm volatile("atom.add.release.gpu.global.u32 %0, [%1], 1;"
                     : "=r"(ticket) : "l"(&g_bar) : "memory");
        u32 target = ((ticket + NCTA) / NCTA) * NCTA;
        u32 cur;
        do {
            asm volatile("ld.acquire.gpu.global.u32 %0, [%1];"
                         : "=r"(cur) : "l"(&g_bar) : "memory");
        } while (cur < target);
    }
    __syncthreads();
}

__device__ __forceinline__ float sigm(float t) { return 1.0f / (1.0f + expf(-t)); }

__device__ __forceinline__ u32 hbits(float w) {
    return (u32)__half_as_ushort(__float2half_rn(w));
}
__device__ __forceinline__ uint2 pack2h(float a, float b, float c, float d) {
    uint2 v;
    v.x = hbits(a) | (hbits(b) << 16);   // b0 (k0, k0+1)
    v.y = hbits(c) | (hbits(d) << 16);   // b1 (k0+8, k0+9)
    return v;
}

// ---------------- cache-policy loads ----------------
__device__ __forceinline__ uint4 ldgA(const uint4* p) {   // read-once streaming
    uint4 v;
    asm volatile("ld.global.L1::no_allocate.v4.u32 {%0,%1,%2,%3}, [%4];"
                 : "=r"(v.x), "=r"(v.y), "=r"(v.z), "=r"(v.w) : "l"(p));
    return v;
}
__device__ __forceinline__ uint4 ldgB4(const uint4* p) {  // constant weights
    uint4 v;
    asm volatile("ld.global.L1::evict_last.v4.u32 {%0,%1,%2,%3}, [%4];"
                 : "=r"(v.x), "=r"(v.y), "=r"(v.z), "=r"(v.w) : "l"(p));
    return v;
}
__device__ __forceinline__ uint2 ldgB2(const uint2* p) {
    uint2 v;
    asm volatile("ld.global.L1::evict_last.v2.u32 {%0,%1}, [%2];"
                 : "=r"(v.x), "=r"(v.y) : "l"(p));
    return v;
}

// A-buffer offset (uint4 units, excluding lane)
__device__ __forceinline__ size_t aoff(int l, int par, int mt, int kt) {
    return (size_t)((((l * 2 + par) * 4 + mt) * 128 + kt)) * 32;
}
// Write activation element (b, c) as fp16 into fragment layout
__device__ __forceinline__ void storeA(int l, int par, int b, int c, float v) {
    int mt = b >> 4, mr = b & 15, kt = c >> 4, kk = c & 15;
    int lane = (mr & 7) * 4 + ((kk & 7) >> 1);
    int slot = (mr >> 3) + ((kk >> 3) << 1);
    __half* p = (__half*)(g_A + aoff(l, par, mt, kt) + lane);
    p[slot * 2 + (kk & 1)] = __float2half_rn(v);
}

// ---------------- mma.m16n8k16 fp16 ----------------
__device__ __forceinline__ void mma_f16(float* d, const uint4& a, u32 b0, u32 b1) {
    asm volatile(
        "mma.sync.aligned.m16n8k16.row.col.f32.f16.f16.f32 "
        "{%0,%1,%2,%3}, {%4,%5,%6,%7}, {%8,%9}, {%0,%1,%2,%3};"
        : "+f"(d[0]), "+f"(d[1]), "+f"(d[2]), "+f"(d[3])
        : "r"(a.x), "r"(a.y), "r"(a.z), "r"(a.w), "r"(b0), "r"(b1));
}
// store a 16x8 tile into smem slab (float[128]) — conflict-free STS.64 pairs
__device__ __forceinline__ void stD1(float* base, int rr, int cc, const float* d) {
    *(float2*)(base + rr * 8 + cc)       = make_float2(d[0], d[1]);
    *(float2*)(base + (rr + 8) * 8 + cc) = make_float2(d[2], d[3]);
}

// SA 8 slices (64 KB) + SB1 (48 KB) + SB2 (48 KB) = 160 KB
#define SMEM_TOTAL ((16384 + 12288 + 12288) * 4)

// ================================================================================
__global__ void __launch_bounds__(NTHR, 1)
decoder_kernel(const int*   __restrict__ y,
               const float* __restrict__ embed,
               const float* __restrict__ W_ih,
               const float* __restrict__ W_hh,
               const float* __restrict__ b_ih,
               const float* __restrict__ b_hh,
               const float* __restrict__ init_state,
               const float* __restrict__ lin_W,
               const float* __restrict__ lin_b,
               float*       __restrict__ out)
{
    extern __shared__ float sbuf[];
    const int tid  = threadIdx.x;
    const int lane = tid & 31;
    const int wid  = tid >> 5;          // 0..15
    const int mhA  = wid & 1;           // job A: m-half (mtiles {0,1} or {2,3})
    const int ksA  = wid >> 1;          // job A: k-slice 0..7 (8 ktiles each)
    const int mpB  = wid & 1;           // jobs L1/L2: m-half
    const int ksB  = wid >> 1;          // jobs L1/L2: k-slice 0..7 (16 ktiles each)
    const int cta  = blockIdx.x;
    const int gt   = cta * NTHR + tid;
    const int GS   = NCTA * NTHR;
    const int rr   = lane >> 2, cc = (lane & 3) << 1;

    // epilogue element owned by this thread
    const int eb   = tid >> 3;          // batch 0..63
    const int ejj  = tid & 7;
    const int emm  = eb >> 4, er2 = eb & 15;
    const int jcol = cta * 8 + ejj;

    // job A view: [s(8)][mt(4)][q(4)][128]
    #define SA(s_, mt, q) (sbuf + (((s_) * 4 + (mt)) * 4 + (q)) * 128)
    // L1/L2 views: [s(8)][mt(4)][g(3)][128]; g=2 holds i_n for s<4, h_n for s>=4
    #define SB1(s_, mt, g) (sbuf + 16384 + (((s_) * 4 + (mt)) * 3 + (g)) * 128)
    #define SB2(s_, mt, g) (sbuf + 28672 + (((s_) * 4 + (mt)) * 3 + (g)) * 128)

    // ================= PROLOGUE =================
    // job A weights, gate-pair fused: half0={r,z}, half1={n, lin}
    for (int idx = gt; idx < 128 * 64 * 2 * 32; idx += GS) {
        int ln = idx & 31, hf = (idx >> 5) & 1, t = (idx >> 6) & 63, ci = idx >> 12;
        int k0 = t * 16 + ((ln & 3) << 1);
        uint2 fr[2];
#pragma unroll
        for (int g = 0; g < 2; ++g) {
            int q = hf * 2 + g;
            int n = q * 1024 + ci * 8 + (ln >> 2);
            const float* src = (n < 3072) ? (W_hh + (size_t)n * 1024)
                                          : (lin_W + (size_t)(n - 3072) * 1024);
            fr[g] = pack2h(src[k0], src[k0 + 1], src[k0 + 8], src[k0 + 9]);
        }
        g_W0q[idx] = make_uint4(fr[0].x, fr[0].y, fr[1].x, fr[1].y);
    }
    // layers 1/2 gates {r,z} fused (K=2048: k<1024 from W_ih, else W_hh)
    for (int idx = gt; idx < 2 * 128 * 128 * 32; idx += GS) {
        int ln = idx & 31, t = (idx >> 5) & 127, ci = (idx >> 12) & 127, ll = idx >> 19;
        int lay = ll + 1;
        int k0 = t * 16 + ((ln & 3) << 1);
        int jj = ci * 8 + (ln >> 2);
        uint2 fr[2];
#pragma unroll
        for (int q = 0; q < 2; ++q) {
            size_t row = (size_t)(lay * 3072 + q * 1024 + jj);
            float w[4];
#pragma unroll
            for (int i = 0; i < 4; ++i) {
                int k = k0 + ((i >> 1) << 3) + (i & 1);   // k0, k0+1, k0+8, k0+9
                w[i] = (k < 1024) ? W_ih[row * 1024 + k] : W_hh[row * 1024 + k - 1024];
            }
            fr[q] = pack2h(w[0], w[1], w[2], w[3]);
        }
        g_W12q4[idx] = make_uint4(fr[0].x, fr[0].y, fr[1].x, fr[1].y);
    }
    // layers 1/2 n-gate merged stream
    for (int idx = gt; idx < 2 * 128 * 128 * 32; idx += GS) {
        int ln = idx & 31, t = (idx >> 5) & 127, ci = (idx >> 12) & 127, ll = idx >> 19;
        int lay = ll + 1;
        int jj = ci * 8 + (ln >> 2);
        size_t row = (size_t)(lay * 3072 + 2048 + jj);
        const float* src;
        int kb;
        if (t < 64) { src = W_ih + row * 1024; kb = t * 16 + ((ln & 3) << 1); }
        else        { src = W_hh + row * 1024; kb = (t - 64) * 16 + ((ln & 3) << 1); }
        g_W12q2[idx] = pack2h(src[kb], src[kb + 1], src[kb + 8], src[kb + 9]);
    }
    // fp32 token table: T[v][row] = embed[v] . W_ih0[row] + b_ih0[row]
    for (int idx = gt; idx < 3072 * 128; idx += GS) {
        int row = idx >> 7, v = idx & 127;
        if (v < NV) {
            const float* e = embed + (size_t)v * 1024;
            const float* w = W_ih + (size_t)row * 1024;
            float a0 = 0, a1 = 0, a2 = 0, a3 = 0;
            for (int k = 0; k < 1024; k += 4) {
                a0 += e[k] * w[k];         a1 += e[k + 1] * w[k + 1];
                a2 += e[k + 2] * w[k + 2]; a3 += e[k + 3] * w[k + 3];
            }
            g_T[v * G3 + row] = (a0 + a1) + (a2 + a3) + b_ih[row];
        }
    }
    // activation init; parity so superphase-0..2 consumers see init values:
    //   h0 read at s=0 (parity 1), h1 read at s=1 (parity 0), h2 read at s=2 (parity 1)
    for (int idx = gt; idx < 3 * 64 * 1024; idx += GS) {
        int l = idx >> 16, r = idx & 65535, b = r >> 10, j = r & 1023;
        float v = init_state[l * 1024 + j];
        int parl = (l == 1) ? 0 : 1;
        storeA(l, parl, b, (l == 0) ? j : (1024 + j), v);
    }

    // ---- per-thread register state + hoisted biases ----
    float h0s = init_state[jcol];
    float h1s = init_state[1024 + jcol];
    float h2s = init_state[2048 + jcol];
    const float bh0r = b_hh[jcol], bh0z = b_hh[1024 + jcol], bh0n = b_hh[2048 + jcol];
    const float bi1r = b_ih[G3 + jcol], bi1z = b_ih[G3 + 1024 + jcol], bi1n = b_ih[G3 + 2048 + jcol];
    const float bh1r = b_hh[G3 + jcol], bh1z = b_hh[G3 + 1024 + jcol], bh1n = b_hh[G3 + 2048 + jcol];
    const float bi2r = b_ih[2 * G3 + jcol], bi2z = b_ih[2 * G3 + 1024 + jcol], bi2n = b_ih[2 * G3 + 2048 + jcol];
    const float bh2r = b_hh[2 * G3 + jcol], bh2z = b_hh[2 * G3 + 1024 + jcol], bh2n = b_hh[2 * G3 + 2048 + jcol];
    const float lb   = lin_b[jcol];

    gridbar();

    // ================= SUPERPHASE LOOP =================
    // superphase s runs: layer0(s), layer1(s-1), layer2(s-2), lin(s-3)
    for (int s = 0; s < NSUP; ++s) {
        const int ps = s & 1, pr = ps ^ 1;

        // ---- prefetch token-table row for layer0(s) (hidden under the GEMMs) ----
        float tv0 = 0.0f, tv1 = 0.0f, tv2 = 0.0f;
        if (s < NSTEPS) {
            int tok = (s == 0) ? (NV - 1) : y[eb * UMX + (s - 1)];
            const float* Tv = g_T + (size_t)tok * G3;
            tv0 = Tv[jcol]; tv1 = Tv[1024 + jcol]; tv2 = Tv[2048 + jcol];
        }

        // ---- job A: layer0 h-GEMM + lin, K=1024; warp = (m-half, k-slice of 8) ----
        {
            const int t0  = ksA * 8;
            const int mt0 = mhA * 2;
            const uint4* A00 = g_A + aoff(0, pr, mt0, t0) + lane;       // A0 mtile mt0
            const uint4* A20 = g_A + aoff(2, pr, mt0, 64 + t0) + lane;  // A2 mtile mt0
            const uint4* BA  = g_W0q + ((size_t)(cta * 64 + t0) * 2) * 32 + lane;
            float d0[4][4] = {};   // mtile mt0: q0..q3
            float d1[4][4] = {};   // mtile mt0+1
#pragma unroll 1
            for (int i = 0; i < 8; i += 2) {
                // batch ALL loads for 2 ktiles (12 independent LDGs)
                uint4 a0_0 = ldgA(A00 + i * 32),        a1_0 = ldgA(A00 + i * 32 + 4096);
                uint4 c0_0 = ldgA(A20 + i * 32),        c1_0 = ldgA(A20 + i * 32 + 4096);
                uint4 p_0  = ldgB4(BA + i * 64),        r_0  = ldgB4(BA + i * 64 + 32);
                uint4 a0_1 = ldgA(A00 + (i + 1) * 32),  a1_1 = ldgA(A00 + (i + 1) * 32 + 4096);
                uint4 c0_1 = ldgA(A20 + (i + 1) * 32),  c1_1 = ldgA(A20 + (i + 1) * 32 + 4096);
                uint4 p_1  = ldgB4(BA + (i + 1) * 64),  r_1  = ldgB4(BA + (i + 1) * 64 + 32);
                mma_f16(d0[0], a0_0, p_0.x, p_0.y);
                mma_f16(d0[1], a0_0, p_0.z, p_0.w);
                mma_f16(d0[2], a0_0, r_0.x, r_0.y);
                mma_f16(d0[3], c0_0, r_0.z, r_0.w);
                mma_f16(d1[0], a1_0, p_0.x, p_0.y);
                mma_f16(d1[1], a1_0, p_0.z, p_0.w);
                mma_f16(d1[2], a1_0, r_0.x, r_0.y);
                mma_f16(d1[3], c1_0, r_0.z, r_0.w);
                mma_f16(d0[0], a0_1, p_1.x, p_1.y);
                mma_f16(d0[1], a0_1, p_1.z, p_1.w);
                mma_f16(d0[2], a0_1, r_1.x, r_1.y);
                mma_f16(d0[3], c0_1, r_1.z, r_1.w);
                mma_f16(d1[0], a1_1, p_1.x, p_1.y);
                mma_f16(d1[1], a1_1, p_1.z, p_1.w);
                mma_f16(d1[2], a1_1, r_1.x, r_1.y);
                mma_f16(d1[3], c1_1, r_1.z, r_1.w);
            }
#pragma unroll
            for (int q = 0; q < 4; ++q) {
                stD1(SA(ksA, mt0, q), rr, cc, d0[q]);
                stD1(SA(ksA, mt0 + 1, q), rr, cc, d1[q]);
            }
        }

        // ---- jobs L1 (layer1(s-1)) and L2 (layer2(s-2)), K=2048 ----
#pragma unroll 1
        for (int l = 1; l <= 2; ++l) {
            const int t0  = ksB * 16;
            const int mt0 = mpB * 2;
            const uint4* A   = g_A + aoff(l, pr, mt0, t0) + lane;
            const uint4* B01 = g_W12q4 + ((size_t)((l - 1) * 128 + cta) * 128 + t0) * 32 + lane;
            const uint2* B23 = g_W12q2 + ((size_t)((l - 1) * 128 + cta) * 128 + t0) * 32 + lane;
            float m0g0[4] = {}, m0g1[4] = {}, m0g2[4] = {};
            float m1g0[4] = {}, m1g1[4] = {}, m1g2[4] = {};
#pragma unroll 1
            for (int i = 0; i < 16; i += 2) {
                // batch ALL loads for 2 ktiles (8 independent LDGs)
                uint4 a0_0 = ldgA(A + i * 32),       a1_0 = ldgA(A + i * 32 + 128 * 32);
                uint4 a0_1 = ldgA(A + (i + 1) * 32), a1_1 = ldgA(A + (i + 1) * 32 + 128 * 32);
                uint4 w_0 = ldgB4(B01 + i * 32), w_1 = ldgB4(B01 + (i + 1) * 32);
                uint2 v_0 = ldgB2(B23 + i * 32), v_1 = ldgB2(B23 + (i + 1) * 32);
                mma_f16(m0g0, a0_0, w_0.x, w_0.y);
                mma_f16(m0g1, a0_0, w_0.z, w_0.w);
                mma_f16(m0g2, a0_0, v_0.x, v_0.y);
                mma_f16(m1g0, a1_0, w_0.x, w_0.y);
                mma_f16(m1g1, a1_0, w_0.z, w_0.w);
                mma_f16(m1g2, a1_0, v_0.x, v_0.y);
                mma_f16(m0g0, a0_1, w_1.x, w_1.y);
                mma_f16(m0g1, a0_1, w_1.z, w_1.w);
                mma_f16(m0g2, a0_1, v_1.x, v_1.y);
                mma_f16(m1g0, a1_1, w_1.x, w_1.y);
                mma_f16(m1g1, a1_1, w_1.z, w_1.w);
                mma_f16(m1g2, a1_1, v_1.x, v_1.y);
            }
            float* s0 = (l == 1) ? SB1(ksB, mt0, 0) : SB2(ksB, mt0, 0);
            float* s1 = (l == 1) ? SB1(ksB, mt0, 1) : SB2(ksB, mt0, 1);
            float* s2 = (l == 1) ? SB1(ksB, mt0, 2) : SB2(ksB, mt0, 2);
            float* s3 = (l == 1) ? SB1(ksB, mt0 + 1, 0) : SB2(ksB, mt0 + 1, 0);
            float* s4 = (l == 1) ? SB1(ksB, mt0 + 1, 1) : SB2(ksB, mt0 + 1, 1);
            float* s5 = (l == 1) ? SB1(ksB, mt0 + 1, 2) : SB2(ksB, mt0 + 1, 2);
            stD1(s0, rr, cc, m0g0);
            stD1(s1, rr, cc, m0g1);
            stD1(s2, rr, cc, m0g2);
            stD1(s3, rr, cc, m1g0);
            stD1(s4, rr, cc, m1g1);
            stD1(s5, rr, cc, m1g2);
        }

        __syncthreads();

        // ---- unified epilogue: lin(s-3), layer0(s), layer1(s-1), layer2(s-2) ----
        {
            // lin(s-3)
            if (s >= 3) {
                float Do = 0;
#pragma unroll
                for (int sl = 0; sl < 8; ++sl) Do += SA(sl, emm, 3)[er2 * 8 + ejj];
                out[(size_t)eb * NSTEPS * 1024 + (size_t)(s - 3) * 1024 + jcol] = Do + lb;
            }
            // layer0(s)
            if (s < NSTEPS) {
                float Dr = 0, Dz = 0, Dn = 0;
#pragma unroll
                for (int sl = 0; sl < 8; ++sl) {
                    Dr += SA(sl, emm, 0)[er2 * 8 + ejj];
                    Dz += SA(sl, emm, 1)[er2 * 8 + ejj];
                    Dn += SA(sl, emm, 2)[er2 * 8 + ejj];
                }
                float r = sigm(tv0 + Dr + bh0r);
                float z = sigm(tv1 + Dz + bh0z);
                float n = tanhf(tv2 + r * (Dn + bh0n));
                h0s = (1.0f - z) * n + z * h0s;
                storeA(1, ps, eb, jcol, h0s);   // x for layer1 (next superphase)
                storeA(0, ps, eb, jcol, h0s);   // h0 (next superphase)
            }
            // layer1(s-1)
            if (s >= 1 && s < NSTEPS + 1) {
                float Gr = 0, Gz = 0, Gi = 0, Gh = 0;
#pragma unroll
                for (int sl = 0; sl < 8; ++sl) {
                    Gr += SB1(sl, emm, 0)[er2 * 8 + ejj];
                    Gz += SB1(sl, emm, 1)[er2 * 8 + ejj];
                }
#pragma unroll
                for (int sl = 0; sl < 4; ++sl) Gi += SB1(sl, emm, 2)[er2 * 8 + ejj];
#pragma unroll
                for (int sl = 4; sl < 8; ++sl) Gh += SB1(sl, emm, 2)[er2 * 8 + ejj];
                float r = sigm(Gr + bi1r + bh1r);
                float z = sigm(Gz + bi1z + bh1z);
                float n = tanhf(Gi + bi1n + r * (Gh + bh1n));
                h1s = (1.0f - z) * n + z * h1s;
                storeA(2, ps, eb, jcol, h1s);          // x for layer2 (next superphase)
                storeA(1, ps, eb, 1024 + jcol, h1s);   // h1 (next superphase)
            }
            // layer2(s-2)
            if (s >= 2 && s < NSTEPS + 2) {
                float Gr = 0, Gz = 0, Gi = 0, Gh = 0;
#pragma unroll
                for (int sl = 0; sl < 8; ++sl) {
                    Gr += SB2(sl, emm, 0)[er2 * 8 + ejj];
                    Gz += SB2(sl, emm, 1)[er2 * 8 + ejj];
                }
#pragma unroll
                for (int sl = 0; sl < 4; ++sl) Gi += SB2(sl, emm, 2)[er2 * 8 + ejj];
#pragma unroll
                for (int sl = 4; sl < 8; ++sl) Gh += SB2(sl, emm, 2)[er2 * 8 + ejj];
                float r = sigm(Gr + bi2r + bh2r);
                float z = sigm(Gz + bi2z + bh2z);
                float n = tanhf(Gi + bi2n + r * (Gh + bh2n));
                h2s = (1.0f - z) * n + z * h2s;
                storeA(2, ps, eb, 1024 + jcol, h2s);   // h2: layer2 + lin (next superphase)
            }
        }
        gridbar();
    }
    #undef SA
    #undef SB1
    #undef SB2
}

extern "C" void kernel_launch(void* const* d_in, const int* in_sizes, int n_in,
                              void* d_out, int out_size) {
    (void)in_sizes; (void)n_in; (void)out_size;
    const int*   y          = (const int*)  d_in[0];
    // d_in[1] = U (unused by the reference math)
    const float* embed      = (const float*)d_in[2];
    const float* W_ih       = (const float*)d_in[3];
    const float* W_hh       = (const float*)d_in[4];
    const float* b_ih       = (const float*)d_in[5];
    const float* b_hh       = (const float*)d_in[6];
    const float* init_state = (const float*)d_in[7];
    const float* lin_W      = (const float*)d_in[8];
    const float* lin_b      = (const float*)d_in[9];
    float* out = (float*)d_out;

    cudaFuncSetAttribute(decoder_kernel,
                         cudaFuncAttributeMaxDynamicSharedMemorySize, SMEM_TOTAL);
    decoder_kernel<<<NCTA, NTHR, SMEM_TOTAL>>>(y, embed, W_ih, W_hh, b_ih, b_hh,
                                               init_state, lin_W, lin_b, out);
}